// round 4
// baseline (speedup 1.0000x reference)
#include <cuda_runtime.h>

#define ITERS 3
#define EPSc 1e-8f
#define LN_EPSc 1e-5f
#define Mc 262144   // B*N
#define BSc 512     // B*S

// scratch (device globals; no allocations allowed)
__device__ float g_xln [67108864];
__device__ float g_kbuf[67108864];
__device__ float g_vbuf[67108864];
__device__ float g_slots[131072];
__device__ float g_sln  [131072];
__device__ float g_q    [131072];
__device__ float g_upd  [131072];
__device__ float g_upd2 [131072];
__device__ float g_ff   [131072];
__device__ float g_h1   [131072];
__device__ float g_xg   [393216];
__device__ float g_hg   [393216];

__global__ void init_slots_kernel(const float* __restrict__ noise,
                                  const float* __restrict__ mean,
                                  const float* __restrict__ logv,
                                  float* __restrict__ slots)
{
    int idx = blockIdx.x * 256 + threadIdx.x;
    int d = idx & 255;
    slots[idx] = mean[d] + expf(logv[d]) * noise[idx];
}

// LayerNorm over D=256, one warp per row
__global__ void ln_rows_kernel(const float* __restrict__ src, float* __restrict__ dst,
                               const float* __restrict__ w, const float* __restrict__ b,
                               int nrows)
{
    int row = blockIdx.x * 8 + (threadIdx.x >> 5);
    if (row >= nrows) return;
    int lane = threadIdx.x & 31;
    const float4* r4 = (const float4*)(src + (size_t)row * 256);
    float4 v0 = r4[lane], v1 = r4[lane + 32];
    float s  = v0.x + v0.y + v0.z + v0.w + v1.x + v1.y + v1.z + v1.w;
    float sq = v0.x*v0.x + v0.y*v0.y + v0.z*v0.z + v0.w*v0.w
             + v1.x*v1.x + v1.y*v1.y + v1.z*v1.z + v1.w*v1.w;
#pragma unroll
    for (int o = 16; o > 0; o >>= 1) {
        s  += __shfl_xor_sync(~0u, s,  o);
        sq += __shfl_xor_sync(~0u, sq, o);
    }
    float mean = s * (1.0f/256.0f);
    float rstd = rsqrtf(sq * (1.0f/256.0f) - mean*mean + LN_EPSc);
    float4 wa = ((const float4*)w)[lane], wb = ((const float4*)w)[lane+32];
    float4 ba = ((const float4*)b)[lane], bb = ((const float4*)b)[lane+32];
    float4 o0, o1;
    o0.x=(v0.x-mean)*rstd*wa.x+ba.x; o0.y=(v0.y-mean)*rstd*wa.y+ba.y;
    o0.z=(v0.z-mean)*rstd*wa.z+ba.z; o0.w=(v0.w-mean)*rstd*wa.w+ba.w;
    o1.x=(v1.x-mean)*rstd*wb.x+bb.x; o1.y=(v1.y-mean)*rstd*wb.y+bb.y;
    o1.z=(v1.z-mean)*rstd*wb.z+bb.z; o1.w=(v1.w-mean)*rstd*wb.w+bb.w;
    float4* d4 = (float4*)(dst + (size_t)row * 256);
    d4[lane] = o0; d4[lane+32] = o1;
}

// K/V projection: C[M,512] = xln[M,256] @ [wk|wv] + bias, scatter to [B,H,N,DH]
__global__ __launch_bounds__(256)
void kv_gemm_kernel(const float* __restrict__ A,
                    const float* __restrict__ Wk, const float* __restrict__ Wv,
                    const float* __restrict__ bk, const float* __restrict__ bv,
                    float* __restrict__ Kout, float* __restrict__ Vout)
{
    __shared__ float As[16][128];
    __shared__ float Bs[16][128];
    int tid = threadIdx.x, tx = tid & 15, ty = tid >> 4;
    int m0 = blockIdx.x * 128, cb = blockIdx.y;
    const float* Wm   = (cb < 2) ? Wk : Wv;
    const float* bias = (cb < 2) ? bk : bv;
    float*       Out  = (cb < 2) ? Kout : Vout;
    int n0 = (cb & 1) * 128;

    float acc[8][8];
#pragma unroll
    for (int i = 0; i < 8; ++i)
#pragma unroll
        for (int j = 0; j < 8; ++j) acc[i][j] = 0.0f;

    for (int kt = 0; kt < 16; ++kt) {
        __syncthreads();
#pragma unroll
        for (int i = 0; i < 2; ++i) {
            int fid = tid*2 + i, ar = fid >> 2, kq = fid & 3;
            float4 va = *(const float4*)(A + (size_t)(m0+ar)*256 + kt*16 + kq*4);
            As[kq*4+0][ar]=va.x; As[kq*4+1][ar]=va.y; As[kq*4+2][ar]=va.z; As[kq*4+3][ar]=va.w;
        }
#pragma unroll
        for (int i = 0; i < 2; ++i) {
            int fid = tid*2 + i, br = fid >> 5, c4 = fid & 31;
            *(float4*)&Bs[br][c4*4] = *(const float4*)(Wm + (size_t)(kt*16+br)*256 + n0 + c4*4);
        }
        __syncthreads();
#pragma unroll
        for (int k = 0; k < 16; ++k) {
            float a[8], bv8[8];
            *(float4*)&a[0]  =*(const float4*)&As[k][ty*8];
            *(float4*)&a[4]  =*(const float4*)&As[k][ty*8+4];
            *(float4*)&bv8[0]=*(const float4*)&Bs[k][tx*8];
            *(float4*)&bv8[4]=*(const float4*)&Bs[k][tx*8+4];
#pragma unroll
            for (int i = 0; i < 8; ++i)
#pragma unroll
                for (int j = 0; j < 8; ++j) acc[i][j] += a[i] * bv8[j];
        }
    }
    int cmat = n0 + tx*8, h = cmat >> 5, dh0 = cmat & 31;
    float bl[8];
#pragma unroll
    for (int j = 0; j < 8; ++j) bl[j] = bias[cmat + j];
#pragma unroll
    for (int i = 0; i < 8; ++i) {
        int m = m0 + ty*8 + i, bi = m >> 12, n = m & 4095;
        float* dst = Out + ((size_t)(bi*8 + h)*4096 + n)*32 + dh0;
        *(float4*)(dst)   = make_float4(acc[i][0]+bl[0],acc[i][1]+bl[1],acc[i][2]+bl[2],acc[i][3]+bl[3]);
        *(float4*)(dst+4) = make_float4(acc[i][4]+bl[4],acc[i][5]+bl[5],acc[i][6]+bl[6],acc[i][7]+bl[7]);
    }
}

// small GEMM: out[512,Ncols] = A[512,256] @ W[256,Ncols] (+bias), modes:
// 0 plain, 1 relu, 2 residual add (Ncols=256), 3 q-layout remap
__global__ __launch_bounds__(256)
void gemm512_kernel(const float* __restrict__ A, const float* __restrict__ W,
                    const float* __restrict__ bias, float* __restrict__ out,
                    int Ncols, int mode, const float* __restrict__ resid)
{
    __shared__ float As[64][36];
    __shared__ float Bs[64][68];
    int tid = threadIdx.x, tx = tid & 31, ty = tid >> 5;
    int c0 = tx*2, r0 = ty*4;
    int m0 = blockIdx.x * 32, n0 = blockIdx.y * 64;
    float acc[4][2] = {};

    for (int kt = 0; kt < 4; ++kt) {
        __syncthreads();
#pragma unroll
        for (int i = 0; i < 2; ++i) {
            int fid = tid*2 + i, ar = fid >> 4, kq = fid & 15;
            float4 va = *(const float4*)(A + (size_t)(m0+ar)*256 + kt*64 + kq*4);
            As[kq*4+0][ar]=va.x; As[kq*4+1][ar]=va.y; As[kq*4+2][ar]=va.z; As[kq*4+3][ar]=va.w;
        }
#pragma unroll
        for (int j = 0; j < 4; ++j) {
            int fid = tid + j*256, br = fid >> 4, c4 = fid & 15;
            *(float4*)&Bs[br][c4*4] = *(const float4*)(W + (size_t)(kt*64+br)*Ncols + n0 + c4*4);
        }
        __syncthreads();
#pragma unroll 8
        for (int k = 0; k < 64; ++k) {
            float4 a4 = *(const float4*)&As[k][r0];
            float2 b2 = *(const float2*)&Bs[k][c0];
            acc[0][0]+=a4.x*b2.x; acc[0][1]+=a4.x*b2.y;
            acc[1][0]+=a4.y*b2.x; acc[1][1]+=a4.y*b2.y;
            acc[2][0]+=a4.z*b2.x; acc[2][1]+=a4.z*b2.y;
            acc[3][0]+=a4.w*b2.x; acc[3][1]+=a4.w*b2.y;
        }
    }
#pragma unroll
    for (int i = 0; i < 4; ++i)
#pragma unroll
        for (int j = 0; j < 2; ++j) {
            int m = m0 + r0 + i, n = n0 + c0 + j;
            float v = acc[i][j] + bias[n];
            if (mode == 0)      out[(size_t)m*Ncols + n] = v;
            else if (mode == 1) out[(size_t)m*Ncols + n] = fmaxf(v, 0.0f);
            else if (mode == 2) out[(size_t)m*256 + n] = resid[(size_t)m*256 + n] + v;
            else {
                int bq = m >> 3, s = m & 7, h = n >> 5, dh = n & 31;
                out[((size_t)(bq*8 + h)*8 + s)*32 + dh] = v;
            }
        }
}

// attention: one CTA per (b,h). Pass1: dots+softmax(S)+eps+row-sum. Pass2: attn@V.
#define ATT_SMEM ((32768 + 256 + 64) * sizeof(float))
__global__ __launch_bounds__(256)
void attention_kernel(const float* __restrict__ q, const float* __restrict__ K,
                      const float* __restrict__ V, float* __restrict__ upd,
                      float* __restrict__ attn_out, int write_attn)
{
    extern __shared__ float sm[];
    float* attn_s = sm;                // [8][4096]
    float* q_s    = sm + 32768;        // [8][32]
    float* red    = sm + 32768 + 256;  // [8][8]
    __shared__ float inv_rs[8];
    int bh = blockIdx.x, tid = threadIdx.x;

    q_s[tid] = q[(size_t)bh*256 + tid] * 0.0625f;  // scale = D^-0.5 = 1/16
    __syncthreads();

    float rs[8] = {};
    const float* Kb = K + (size_t)bh * 4096 * 32;
    for (int it = 0; it < 16; ++it) {
        int n = it*256 + tid;
        const float4* kr = (const float4*)(Kb + (size_t)n * 32);
        float d[8] = {};
#pragma unroll
        for (int c = 0; c < 8; ++c) {
            float4 kk = kr[c];
#pragma unroll
            for (int s = 0; s < 8; ++s) {
                float4 qv = *(const float4*)(q_s + s*32 + c*4);
                d[s] += kk.x*qv.x + kk.y*qv.y + kk.z*qv.z + kk.w*qv.w;
            }
        }
        float mx = d[0];
#pragma unroll
        for (int s = 1; s < 8; ++s) mx = fmaxf(mx, d[s]);
        float e[8], sum = 0.0f;
#pragma unroll
        for (int s = 0; s < 8; ++s) { e[s] = __expf(d[s]-mx); sum += e[s]; }
        float inv = __fdividef(1.0f, sum);
#pragma unroll
        for (int s = 0; s < 8; ++s) {
            float p = e[s]*inv + EPSc;
            attn_s[s*4096 + n] = p;
            rs[s] += p;
        }
    }
#pragma unroll
    for (int s = 0; s < 8; ++s)
#pragma unroll
        for (int o = 16; o > 0; o >>= 1) rs[s] += __shfl_xor_sync(~0u, rs[s], o);
    int lane = tid & 31, wid = tid >> 5;
    if (lane == 0)
#pragma unroll
        for (int s = 0; s < 8; ++s) red[wid*8 + s] = rs[s];
    __syncthreads();
    if (tid < 8) {
        float t = 0.0f;
#pragma unroll
        for (int w = 0; w < 8; ++w) t += red[w*8 + tid];
        inv_rs[tid] = 1.0f / fmaxf(t, 1e-12f);
    }
    __syncthreads();

    {
        int s = tid >> 5, dh = tid & 31;
        const float* Vb = V + (size_t)bh * 4096 * 32 + dh;
        const float* as = attn_s + s*4096;
        float a0 = 0.0f, a1 = 0.0f;
        for (int n = 0; n < 4096; n += 8) {
            float4 p0 = *(const float4*)(as + n);
            float4 p1 = *(const float4*)(as + n + 4);
            a0 += p0.x*Vb[(size_t)(n+0)*32] + p0.y*Vb[(size_t)(n+1)*32]
                + p0.z*Vb[(size_t)(n+2)*32] + p0.w*Vb[(size_t)(n+3)*32];
            a1 += p1.x*Vb[(size_t)(n+4)*32] + p1.y*Vb[(size_t)(n+5)*32]
                + p1.z*Vb[(size_t)(n+6)*32] + p1.w*Vb[(size_t)(n+7)*32];
        }
        int b = bh >> 3, h = bh & 7;
        upd[(size_t)(b*8 + s)*256 + h*32 + dh] = (a0 + a1) * inv_rs[s];
    }

    if (write_attn) {
        float* ao = attn_out + (size_t)bh * 32768;
        for (int i = tid; i < 32768; i += 256)
            ao[i] = attn_s[i] * inv_rs[i >> 12];
    }
}

__global__ void gru_combine_kernel(const float* __restrict__ xg,
                                   const float* __restrict__ hg,
                                   float* __restrict__ slots)
{
    int idx = blockIdx.x * 256 + threadIdx.x;
    int row = idx >> 8, c = idx & 255;
    const float* x = xg + (size_t)row * 768;
    const float* h = hg + (size_t)row * 768;
    float r = 1.0f / (1.0f + expf(-(x[c]     + h[c])));
    float z = 1.0f / (1.0f + expf(-(x[256+c] + h[256+c])));
    float n = tanhf(x[512+c] + r * h[512+c]);
    slots[idx] = (1.0f - z) * n + z * slots[idx];
}

extern "C" void kernel_launch(void* const* d_in, const int* in_sizes, int n_in,
                              void* d_out, int out_size)
{
    const float* inp   = (const float*)d_in[0];
    const float* noise = (const float*)d_in[1];
    const float* smean = (const float*)d_in[2];
    const float* slogv = (const float*)d_in[3];
    const float* wq = (const float*)d_in[4];  const float* bq = (const float*)d_in[5];
    const float* wk = (const float*)d_in[6];  const float* bk = (const float*)d_in[7];
    const float* wv = (const float*)d_in[8];  const float* bv = (const float*)d_in[9];
    const float* wo = (const float*)d_in[10]; const float* bo = (const float*)d_in[11];
    const float* w_ih = (const float*)d_in[12]; const float* b_ih = (const float*)d_in[13];
    const float* w_hh = (const float*)d_in[14]; const float* b_hh = (const float*)d_in[15];
    const float* w1 = (const float*)d_in[16]; const float* b1 = (const float*)d_in[17];
    const float* w2 = (const float*)d_in[18]; const float* b2 = (const float*)d_in[19];
    const float* lin_w = (const float*)d_in[20]; const float* lin_b = (const float*)d_in[21];
    const float* ls_w  = (const float*)d_in[22]; const float* ls_b  = (const float*)d_in[23];
    const float* lff_w = (const float*)d_in[24]; const float* lff_b = (const float*)d_in[25];

    float* out      = (float*)d_out;       // slots [B,S,D]
    float* attn_out = out + 131072;        // attn [B,H,S,N]

    float *xln,*kb,*vb,*slots,*sln,*qb,*upd,*upd2,*ff,*h1,*xg,*hg;
    cudaGetSymbolAddress((void**)&xln,  g_xln);
    cudaGetSymbolAddress((void**)&kb,   g_kbuf);
    cudaGetSymbolAddress((void**)&vb,   g_vbuf);
    cudaGetSymbolAddress((void**)&slots,g_slots);
    cudaGetSymbolAddress((void**)&sln,  g_sln);
    cudaGetSymbolAddress((void**)&qb,   g_q);
    cudaGetSymbolAddress((void**)&upd,  g_upd);
    cudaGetSymbolAddress((void**)&upd2, g_upd2);
    cudaGetSymbolAddress((void**)&ff,   g_ff);
    cudaGetSymbolAddress((void**)&h1,   g_h1);
    cudaGetSymbolAddress((void**)&xg,   g_xg);
    cudaGetSymbolAddress((void**)&hg,   g_hg);

    cudaFuncSetAttribute(attention_kernel,
                         cudaFuncAttributeMaxDynamicSharedMemorySize, (int)ATT_SMEM);

    init_slots_kernel<<<BSc, 256>>>(noise, smean, slogv, slots);
    ln_rows_kernel<<<Mc/8, 256>>>(inp, xln, lin_w, lin_b, Mc);
    kv_gemm_kernel<<<dim3(Mc/128, 4), 256>>>(xln, wk, wv, bk, bv, kb, vb);

    for (int it = 0; it < ITERS; ++it) {
        int last = (it == ITERS - 1);
        ln_rows_kernel<<<BSc/8, 256>>>(slots, sln, ls_w, ls_b, BSc);
        gemm512_kernel<<<dim3(16, 4), 256>>>(sln, wq, bq, qb, 256, 3, nullptr);
        attention_kernel<<<512, 256, ATT_SMEM>>>(qb, kb, vb, upd, attn_out, last);
        gemm512_kernel<<<dim3(16, 4), 256>>>(upd, wo, bo, upd2, 256, 0, nullptr);
        gemm512_kernel<<<dim3(16, 12), 256>>>(upd2, w_ih, b_ih, xg, 768, 0, nullptr);
        gemm512_kernel<<<dim3(16, 12), 256>>>(slots, w_hh, b_hh, hg, 768, 0, nullptr);
        gru_combine_kernel<<<BSc, 256>>>(xg, hg, slots);
        ln_rows_kernel<<<BSc/8, 256>>>(slots, ff, lff_w, lff_b, BSc);
        gemm512_kernel<<<dim3(16, 4), 256>>>(ff, w1, b1, h1, 256, 1, nullptr);
        gemm512_kernel<<<dim3(16, 4), 256>>>(h1, w2, b2, last ? out : slots, 256, 2, slots);
    }
}

// round 6
// speedup vs baseline: 1.7946x; 1.7946x over previous
#include <cuda_runtime.h>
#include <cuda_bf16.h>
#include <cstdint>

#define ITERS 3
#define EPSc 1e-8f
#define LN_EPSc 1e-5f
#define Mc 262144   // B*N
#define BSc 512     // B*S

// ---------------- scratch (device globals) ----------------------------------
__device__ __nv_bfloat16 g_a2 [134217728]; // [M,512] = [hi(256) | lo(256)] of LN(x)
__device__ __nv_bfloat16 g_wb2[262144];    // [512 n][512 k] = [hi | lo] K-major
__device__ float g_kbuf[67108864];         // K [B,H,N,DH]
__device__ float g_vbuf[67108864];         // V
__device__ float g_slots[131072];
__device__ float g_sln  [131072];
__device__ float g_q    [131072];
__device__ float g_upd  [131072];
__device__ float g_upd2 [131072];
__device__ float g_ff   [131072];
__device__ float g_h1   [131072];
__device__ float g_xg   [393216];
__device__ float g_hg   [393216];

// ---------------- misc small kernels -----------------------------------------
__global__ void init_slots_kernel(const float* __restrict__ noise,
                                  const float* __restrict__ mean,
                                  const float* __restrict__ logv,
                                  float* __restrict__ slots)
{
    int idx = blockIdx.x * 256 + threadIdx.x;
    int d = idx & 255;
    slots[idx] = mean[d] + expf(logv[d]) * noise[idx];
}

// LN over D=256 (fp32 out) — slot-side LNs
__global__ void ln_rows_kernel(const float* __restrict__ src, float* __restrict__ dst,
                               const float* __restrict__ w, const float* __restrict__ b,
                               int nrows)
{
    int row = blockIdx.x * 8 + (threadIdx.x >> 5);
    if (row >= nrows) return;
    int lane = threadIdx.x & 31;
    const float4* r4 = (const float4*)(src + (size_t)row * 256);
    float4 v0 = r4[lane], v1 = r4[lane + 32];
    float s  = v0.x + v0.y + v0.z + v0.w + v1.x + v1.y + v1.z + v1.w;
    float sq = v0.x*v0.x + v0.y*v0.y + v0.z*v0.z + v0.w*v0.w
             + v1.x*v1.x + v1.y*v1.y + v1.z*v1.z + v1.w*v1.w;
#pragma unroll
    for (int o = 16; o > 0; o >>= 1) {
        s  += __shfl_xor_sync(~0u, s,  o);
        sq += __shfl_xor_sync(~0u, sq, o);
    }
    float mean = s * (1.0f/256.0f);
    float rstd = rsqrtf(sq * (1.0f/256.0f) - mean*mean + LN_EPSc);
    float4 wa = ((const float4*)w)[lane], wb = ((const float4*)w)[lane+32];
    float4 ba = ((const float4*)b)[lane], bb = ((const float4*)b)[lane+32];
    float4 o0, o1;
    o0.x=(v0.x-mean)*rstd*wa.x+ba.x; o0.y=(v0.y-mean)*rstd*wa.y+ba.y;
    o0.z=(v0.z-mean)*rstd*wa.z+ba.z; o0.w=(v0.w-mean)*rstd*wa.w+ba.w;
    o1.x=(v1.x-mean)*rstd*wb.x+bb.x; o1.y=(v1.y-mean)*rstd*wb.y+bb.y;
    o1.z=(v1.z-mean)*rstd*wb.z+bb.z; o1.w=(v1.w-mean)*rstd*wb.w+bb.w;
    float4* d4 = (float4*)(dst + (size_t)row * 256);
    d4[lane] = o0; d4[lane+32] = o1;
}

// LN(inputs) fused with bf16 hi/lo split -> g_a2 [M,512]
__device__ __forceinline__ void split4_store(__nv_bfloat16* dst, float4 o) {
    __nv_bfloat16 hx = __float2bfloat16(o.x), hy = __float2bfloat16(o.y);
    __nv_bfloat16 hz = __float2bfloat16(o.z), hw = __float2bfloat16(o.w);
    __nv_bfloat162 h0; h0.x = hx; h0.y = hy;
    __nv_bfloat162 h1; h1.x = hz; h1.y = hw;
    ((__nv_bfloat162*)dst)[0] = h0;
    ((__nv_bfloat162*)dst)[1] = h1;
    __nv_bfloat162 l0, l1;
    l0.x = __float2bfloat16(o.x - __bfloat162float(hx));
    l0.y = __float2bfloat16(o.y - __bfloat162float(hy));
    l1.x = __float2bfloat16(o.z - __bfloat162float(hz));
    l1.y = __float2bfloat16(o.w - __bfloat162float(hw));
    ((__nv_bfloat162*)(dst + 256))[0] = l0;
    ((__nv_bfloat162*)(dst + 256))[1] = l1;
}
__global__ void ln_kv_kernel(const float* __restrict__ src, __nv_bfloat16* __restrict__ dst,
                             const float* __restrict__ w, const float* __restrict__ b)
{
    int row = blockIdx.x * 8 + (threadIdx.x >> 5);
    int lane = threadIdx.x & 31;
    const float4* r4 = (const float4*)(src + (size_t)row * 256);
    float4 v0 = r4[lane], v1 = r4[lane + 32];
    float s  = v0.x + v0.y + v0.z + v0.w + v1.x + v1.y + v1.z + v1.w;
    float sq = v0.x*v0.x + v0.y*v0.y + v0.z*v0.z + v0.w*v0.w
             + v1.x*v1.x + v1.y*v1.y + v1.z*v1.z + v1.w*v1.w;
#pragma unroll
    for (int o = 16; o > 0; o >>= 1) {
        s  += __shfl_xor_sync(~0u, s,  o);
        sq += __shfl_xor_sync(~0u, sq, o);
    }
    float mean = s * (1.0f/256.0f);
    float rstd = rsqrtf(sq * (1.0f/256.0f) - mean*mean + LN_EPSc);
    float4 wa = ((const float4*)w)[lane], wb = ((const float4*)w)[lane+32];
    float4 ba = ((const float4*)b)[lane], bb = ((const float4*)b)[lane+32];
    float4 o0, o1;
    o0.x=(v0.x-mean)*rstd*wa.x+ba.x; o0.y=(v0.y-mean)*rstd*wa.y+ba.y;
    o0.z=(v0.z-mean)*rstd*wa.z+ba.z; o0.w=(v0.w-mean)*rstd*wa.w+ba.w;
    o1.x=(v1.x-mean)*rstd*wb.x+bb.x; o1.y=(v1.y-mean)*rstd*wb.y+bb.y;
    o1.z=(v1.z-mean)*rstd*wb.z+bb.z; o1.w=(v1.w-mean)*rstd*wb.w+bb.w;
    __nv_bfloat16* dr = dst + (size_t)row * 512;
    split4_store(dr + lane*4,       o0);
    split4_store(dr + 128 + lane*4, o1);
}

// W -> [n][k] K-major bf16 hi/lo (n<256: wk, else wv)
__global__ void prep_w_kernel(const float* __restrict__ wk, const float* __restrict__ wv,
                              __nv_bfloat16* __restrict__ B2)
{
    int n = blockIdx.x;          // 0..511
    int k = threadIdx.x;         // 0..255
    const float* W = (n < 256) ? wk : wv;
    float x = W[(size_t)k * 256 + (n & 255)];
    __nv_bfloat16 h = __float2bfloat16(x);
    B2[(size_t)n * 512 + k]       = h;
    B2[(size_t)n * 512 + 256 + k] = __float2bfloat16(x - __bfloat162float(h));
}

// ---------------- K/V GEMM via mma.sync bf16 ---------------------------------
// D[128m,128n] per CTA; hi/lo compensation via 12 K-chunks of 64 (K_eff=768).
// grid=(4,2048): x = cb (matrix 0=K/1=V, n-half), y = m-block (so the 4 column
// variants of the same A rows are adjacent in schedule order -> L2 reuse).
#define AST 72   // smem row stride in bf16 (conflict-free fragment loads)
__global__ __launch_bounds__(256)
void kv_gemm_mma(const __nv_bfloat16* __restrict__ A2, const __nv_bfloat16* __restrict__ B2,
                 const float* __restrict__ bk, const float* __restrict__ bv,
                 float* __restrict__ Kout, float* __restrict__ Vout)
{
    __shared__ __nv_bfloat16 As[128 * AST];
    __shared__ __nv_bfloat16 Bs[128 * AST];
    int tid = threadIdx.x, lane = tid & 31, wid = tid >> 5;
    int warp_m = wid & 1, warp_n = wid >> 1;       // 2 x 4 warps
    int cb  = blockIdx.x;                          // 0..3
    int m0  = blockIdx.y * 128;
    int mat = cb >> 1, nh = cb & 1;
    const float* bias = mat ? bv : bk;
    float* Out = mat ? Vout : Kout;

    float acc[4][4][4];
#pragma unroll
    for (int a = 0; a < 4; ++a)
#pragma unroll
        for (int b = 0; b < 4; ++b)
#pragma unroll
            for (int r = 0; r < 4; ++r) acc[a][b][r] = 0.0f;

    const int a_k[12] = {0,64,128,192, 0,64,128,192, 256,320,384,448};
    const int b_k[12] = {0,64,128,192, 256,320,384,448, 0,64,128,192};

    for (int c = 0; c < 12; ++c) {
        __syncthreads();
#pragma unroll
        for (int i = 0; i < 4; ++i) {
            int fid = tid + i * 256, r = fid >> 3, j = fid & 7;
            float4 v = *(const float4*)(A2 + (size_t)(m0 + r) * 512 + a_k[c] + j * 8);
            *(float4*)(As + r * AST + j * 8) = v;
        }
#pragma unroll
        for (int i = 0; i < 4; ++i) {
            int fid = tid + i * 256, r = fid >> 3, j = fid & 7;
            float4 v = *(const float4*)(B2 + (size_t)(mat * 256 + nh * 128 + r) * 512 + b_k[c] + j * 8);
            *(float4*)(Bs + r * AST + j * 8) = v;
        }
        __syncthreads();
#pragma unroll
        for (int ks = 0; ks < 4; ++ks) {
            int krow = ks * 16 + (lane & 3) * 2;
            uint32_t af[4][4], bf[4][2];
#pragma unroll
            for (int mt = 0; mt < 4; ++mt) {
                const __nv_bfloat16* p = As + (warp_m * 64 + mt * 16 + (lane >> 2)) * AST;
                af[mt][0] = *(const uint32_t*)(p + krow);
                af[mt][1] = *(const uint32_t*)(p + 8 * AST + krow);
                af[mt][2] = *(const uint32_t*)(p + krow + 8);
                af[mt][3] = *(const uint32_t*)(p + 8 * AST + krow + 8);
            }
#pragma unroll
            for (int nt = 0; nt < 4; ++nt) {
                const __nv_bfloat16* p = Bs + (warp_n * 32 + nt * 8 + (lane >> 2)) * AST;
                bf[nt][0] = *(const uint32_t*)(p + krow);
                bf[nt][1] = *(const uint32_t*)(p + krow + 8);
            }
#pragma unroll
            for (int mt = 0; mt < 4; ++mt)
#pragma unroll
                for (int nt = 0; nt < 4; ++nt)
                    asm volatile(
                        "mma.sync.aligned.m16n8k16.row.col.f32.bf16.bf16.f32 "
                        "{%0,%1,%2,%3}, {%4,%5,%6,%7}, {%8,%9}, {%0,%1,%2,%3};"
                        : "+f"(acc[mt][nt][0]), "+f"(acc[mt][nt][1]),
                          "+f"(acc[mt][nt][2]), "+f"(acc[mt][nt][3])
                        : "r"(af[mt][0]), "r"(af[mt][1]), "r"(af[mt][2]), "r"(af[mt][3]),
                          "r"(bf[nt][0]), "r"(bf[nt][1]));
        }
    }

    // epilogue: scatter to [B,H,N,DH]; this warp writes head h = nh*4 + warp_n
    int col_base = nh * 128 + warp_n * 32;
    int h = col_base >> 5;
#pragma unroll
    for (int mt = 0; mt < 4; ++mt) {
#pragma unroll
        for (int half = 0; half < 2; ++half) {
            int m = m0 + warp_m * 64 + mt * 16 + (lane >> 2) + half * 8;
            int bi = m >> 12, nn = m & 4095;
            float* dst = Out + ((size_t)(bi * 8 + h) * 4096 + nn) * 32;
#pragma unroll
            for (int nt = 0; nt < 4; ++nt) {
                int dh = nt * 8 + (lane & 3) * 2;
                float2 o;
                o.x = acc[mt][nt][half * 2 + 0] + bias[col_base + dh];
                o.y = acc[mt][nt][half * 2 + 1] + bias[col_base + dh + 1];
                *(float2*)(dst + dh) = o;
            }
        }
    }
}

// ---------------- small GEMM (512 rows) --------------------------------------
__global__ __launch_bounds__(256)
void gemm512_kernel(const float* __restrict__ A, const float* __restrict__ W,
                    const float* __restrict__ bias, float* __restrict__ out,
                    int Ncols, int mode, const float* __restrict__ resid)
{
    __shared__ float As[64][36];
    __shared__ float Bs[64][68];
    int tid = threadIdx.x, tx = tid & 31, ty = tid >> 5;
    int c0 = tx*2, r0 = ty*4;
    int m0 = blockIdx.x * 32, n0 = blockIdx.y * 64;
    float acc[4][2] = {};

    for (int kt = 0; kt < 4; ++kt) {
        __syncthreads();
#pragma unroll
        for (int i = 0; i < 2; ++i) {
            int fid = tid*2 + i, ar = fid >> 4, kq = fid & 15;
            float4 va = *(const float4*)(A + (size_t)(m0+ar)*256 + kt*64 + kq*4);
            As[kq*4+0][ar]=va.x; As[kq*4+1][ar]=va.y; As[kq*4+2][ar]=va.z; As[kq*4+3][ar]=va.w;
        }
#pragma unroll
        for (int j = 0; j < 4; ++j) {
            int fid = tid + j*256, br = fid >> 4, c4 = fid & 15;
            *(float4*)&Bs[br][c4*4] = *(const float4*)(W + (size_t)(kt*64+br)*Ncols + n0 + c4*4);
        }
        __syncthreads();
#pragma unroll 8
        for (int k = 0; k < 64; ++k) {
            float4 a4 = *(const float4*)&As[k][r0];
            float2 b2 = *(const float2*)&Bs[k][c0];
            acc[0][0]+=a4.x*b2.x; acc[0][1]+=a4.x*b2.y;
            acc[1][0]+=a4.y*b2.x; acc[1][1]+=a4.y*b2.y;
            acc[2][0]+=a4.z*b2.x; acc[2][1]+=a4.z*b2.y;
            acc[3][0]+=a4.w*b2.x; acc[3][1]+=a4.w*b2.y;
        }
    }
#pragma unroll
    for (int i = 0; i < 4; ++i)
#pragma unroll
        for (int j = 0; j < 2; ++j) {
            int m = m0 + r0 + i, n = n0 + c0 + j;
            float v = acc[i][j] + bias[n];
            if (mode == 0)      out[(size_t)m*Ncols + n] = v;
            else if (mode == 1) out[(size_t)m*Ncols + n] = fmaxf(v, 0.0f);
            else if (mode == 2) out[(size_t)m*256 + n] = resid[(size_t)m*256 + n] + v;
            else {
                int bq = m >> 3, s = m & 7, h = n >> 5, dh = n & 31;
                out[((size_t)(bq*8 + h)*8 + s)*32 + dh] = v;
            }
        }
}

// ---------------- attention ---------------------------------------------------
#define ATT_SMEM ((32768 + 256 + 64 + 2048) * sizeof(float))
__global__ __launch_bounds__(256)
void attention_kernel(const float* __restrict__ q, const float* __restrict__ K,
                      const float* __restrict__ V, float* __restrict__ upd,
                      float* __restrict__ attn_out, int write_attn)
{
    extern __shared__ float sm[];
    float* attn_s = sm;                    // [8][4096]
    float* q_s    = sm + 32768;            // [8][32]
    float* red    = sm + 32768 + 256;      // [8][8]
    float* red2   = sm + 32768 + 256 + 64; // [8 warps][8 s][32 dh]
    __shared__ float inv_rs[8];
    int bh = blockIdx.x, tid = threadIdx.x;
    int lane = tid & 31, wid = tid >> 5;

    q_s[tid] = q[(size_t)bh*256 + tid] * 0.0625f;  // scale = D^-0.5 = 1/16
    __syncthreads();

    float rs[8] = {};
    const float* Kb = K + (size_t)bh * 4096 * 32;
    for (int it = 0; it < 16; ++it) {
        int n = it*256 + tid;
        const float4* kr = (const float4*)(Kb + (size_t)n * 32);
        float d[8] = {};
#pragma unroll
        for (int c = 0; c < 8; ++c) {
            float4 kk = kr[c];
#pragma unroll
            for (int s = 0; s < 8; ++s) {
                float4 qv = *(const float4*)(q_s + s*32 + c*4);
                d[s] += kk.x*qv.x + kk.y*qv.y + kk.z*qv.z + kk.w*qv.w;
            }
        }
        float mx = d[0];
#pragma unroll
        for (int s = 1; s < 8; ++s) mx = fmaxf(mx, d[s]);
        float e[8], sum = 0.0f;
#pragma unroll
        for (int s = 0; s < 8; ++s) { e[s] = __expf(d[s]-mx); sum += e[s]; }
        float inv = __fdividef(1.0f, sum);
#pragma unroll
        for (int s = 0; s < 8; ++s) {
            float p = e[s]*inv + EPSc;
            attn_s[s*4096 + n] = p;
            rs[s] += p;
        }
    }
#pragma unroll
    for (int s = 0; s < 8; ++s)
#pragma unroll
        for (int o = 16; o > 0; o >>= 1) rs[s] += __shfl_xor_sync(~0u, rs[s], o);
    if (lane == 0)
#pragma unroll
        for (int s = 0; s < 8; ++s) red[wid*8 + s] = rs[s];
    __syncthreads();
    if (tid < 8) {
        float t = 0.0f;
#pragma unroll
        for (int w = 0; w < 8; ++w) t += red[w*8 + tid];
        inv_rs[tid] = 1.0f / fmaxf(t, 1e-12f);
    }

    // pass2: warp w owns n-stripe [w*512, w*512+512); V read once per CTA.
    {
        const float* Vb = V + (size_t)bh * 4096 * 32;
        float acc[8] = {};
        int nb = wid * 512;
        for (int n = nb; n < nb + 512; n += 4) {
            float4 a[8];
#pragma unroll
            for (int s = 0; s < 8; ++s) a[s] = *(const float4*)(attn_s + s*4096 + n);
            float v0 = Vb[(size_t)(n+0)*32 + lane];
            float v1 = Vb[(size_t)(n+1)*32 + lane];
            float v2 = Vb[(size_t)(n+2)*32 + lane];
            float v3 = Vb[(size_t)(n+3)*32 + lane];
#pragma unroll
            for (int s = 0; s < 8; ++s)
                acc[s] += a[s].x*v0 + a[s].y*v1 + a[s].z*v2 + a[s].w*v3;
        }
#pragma unroll
        for (int s = 0; s < 8; ++s) red2[(wid*8 + s)*32 + lane] = acc[s];
    }
    __syncthreads();
    {
        int s = tid >> 5, dh = tid & 31;
        float t = 0.0f;
#pragma unroll
        for (int w = 0; w < 8; ++w) t += red2[(w*8 + s)*32 + dh];
        int b = bh >> 3, h = bh & 7;
        upd[(size_t)(b*8 + s)*256 + h*32 + dh] = t * inv_rs[s];
    }

    if (write_attn) {
        float* ao = attn_out + (size_t)bh * 32768;
        for (int i = tid; i < 32768; i += 256)
            ao[i] = attn_s[i] * inv_rs[i >> 12];
    }
}

__global__ void gru_combine_kernel(const float* __restrict__ xg,
                                   const float* __restrict__ hg,
                                   float* __restrict__ slots)
{
    int idx = blockIdx.x * 256 + threadIdx.x;
    int row = idx >> 8, c = idx & 255;
    const float* x = xg + (size_t)row * 768;
    const float* h = hg + (size_t)row * 768;
    float r = 1.0f / (1.0f + expf(-(x[c]     + h[c])));
    float z = 1.0f / (1.0f + expf(-(x[256+c] + h[256+c])));
    float n = tanhf(x[512+c] + r * h[512+c]);
    slots[idx] = (1.0f - z) * n + z * slots[idx];
}

// ---------------- launcher ----------------------------------------------------
extern "C" void kernel_launch(void* const* d_in, const int* in_sizes, int n_in,
                              void* d_out, int out_size)
{
    const float* inp   = (const float*)d_in[0];
    const float* noise = (const float*)d_in[1];
    const float* smean = (const float*)d_in[2];
    const float* slogv = (const float*)d_in[3];
    const float* wq = (const float*)d_in[4];  const float* bq = (const float*)d_in[5];
    const float* wk = (const float*)d_in[6];  const float* bk = (const float*)d_in[7];
    const float* wv = (const float*)d_in[8];  const float* bv = (const float*)d_in[9];
    const float* wo = (const float*)d_in[10]; const float* bo = (const float*)d_in[11];
    const float* w_ih = (const float*)d_in[12]; const float* b_ih = (const float*)d_in[13];
    const float* w_hh = (const float*)d_in[14]; const float* b_hh = (const float*)d_in[15];
    const float* w1 = (const float*)d_in[16]; const float* b1 = (const float*)d_in[17];
    const float* w2 = (const float*)d_in[18]; const float* b2 = (const float*)d_in[19];
    const float* lin_w = (const float*)d_in[20]; const float* lin_b = (const float*)d_in[21];
    const float* ls_w  = (const float*)d_in[22]; const float* ls_b  = (const float*)d_in[23];
    const float* lff_w = (const float*)d_in[24]; const float* lff_b = (const float*)d_in[25];

    float* out      = (float*)d_out;
    float* attn_out = out + 131072;

    __nv_bfloat16 *a2, *wb2;
    float *kb,*vb,*slots,*sln,*qb,*upd,*upd2,*ff,*h1,*xg,*hg;
    cudaGetSymbolAddress((void**)&a2,   g_a2);
    cudaGetSymbolAddress((void**)&wb2,  g_wb2);
    cudaGetSymbolAddress((void**)&kb,   g_kbuf);
    cudaGetSymbolAddress((void**)&vb,   g_vbuf);
    cudaGetSymbolAddress((void**)&slots,g_slots);
    cudaGetSymbolAddress((void**)&sln,  g_sln);
    cudaGetSymbolAddress((void**)&qb,   g_q);
    cudaGetSymbolAddress((void**)&upd,  g_upd);
    cudaGetSymbolAddress((void**)&upd2, g_upd2);
    cudaGetSymbolAddress((void**)&ff,   g_ff);
    cudaGetSymbolAddress((void**)&h1,   g_h1);
    cudaGetSymbolAddress((void**)&xg,   g_xg);
    cudaGetSymbolAddress((void**)&hg,   g_hg);

    cudaFuncSetAttribute(attention_kernel,
                         cudaFuncAttributeMaxDynamicSharedMemorySize, (int)ATT_SMEM);

    init_slots_kernel<<<BSc, 256>>>(noise, smean, slogv, slots);
    prep_w_kernel<<<512, 256>>>(wk, wv, wb2);
    ln_kv_kernel<<<Mc/8, 256>>>(inp, a2, lin_w, lin_b);
    kv_gemm_mma<<<dim3(4, Mc/128), 256>>>(a2, wb2, bk, bv, kb, vb);

    for (int it = 0; it < ITERS; ++it) {
        int last = (it == ITERS - 1);
        ln_rows_kernel<<<BSc/8, 256>>>(slots, sln, ls_w, ls_b, BSc);
        gemm512_kernel<<<dim3(16, 4), 256>>>(sln, wq, bq, qb, 256, 3, nullptr);
        attention_kernel<<<512, 256, ATT_SMEM>>>(qb, kb, vb, upd, attn_out, last);
        gemm512_kernel<<<dim3(16, 4), 256>>>(upd, wo, bo, upd2, 256, 0, nullptr);
        gemm512_kernel<<<dim3(16, 12), 256>>>(upd2, w_ih, b_ih, xg, 768, 0, nullptr);
        gemm512_kernel<<<dim3(16, 12), 256>>>(slots, w_hh, b_hh, hg, 768, 0, nullptr);
        gru_combine_kernel<<<BSc, 256>>>(xg, hg, slots);
        ln_rows_kernel<<<BSc/8, 256>>>(slots, ff, lff_w, lff_b, BSc);
        gemm512_kernel<<<dim3(16, 4), 256>>>(ff, w1, b1, h1, 256, 1, nullptr);
        gemm512_kernel<<<dim3(16, 4), 256>>>(h1, w2, b2, last ? out : slots, 256, 2, slots);
    }
}

// round 7
// speedup vs baseline: 2.0107x; 1.1204x over previous
#include <cuda_runtime.h>
#include <cuda_bf16.h>
#include <cstdint>

#define ITERS 3
#define EPSc 1e-8f
#define LN_EPSc 1e-5f
#define Mc 262144   // B*N
#define BSc 512     // B*S

// ---------------- scratch (device globals) ----------------------------------
__device__ __nv_bfloat16 g_a2 [134217728]; // [M,512] = [hi(256) | lo(256)] of LN(x)
__device__ __nv_bfloat16 g_wb2[262144];    // [512 n][512 k] = [hi | lo] K-major
__device__ float         g_kbuf[67108864]; // K [B,H,N,DH] fp32
__device__ __nv_bfloat16 g_vbufh[67108864];// V [B,H,N,DH] bf16
__device__ float g_slots[131072];
__device__ float g_q    [131072];
__device__ float g_upd  [131072];
__device__ float g_upd2 [131072];
__device__ float g_h1   [131072];
__device__ float g_xg   [393216];
__device__ float g_hg   [393216];

__device__ __forceinline__ uint32_t smem_u32(const void* p) {
    uint32_t a;
    asm("{ .reg .u64 t; cvta.to.shared.u64 t, %1; cvt.u32.u64 %0, t; }" : "=r"(a) : "l"(p));
    return a;
}
__device__ __forceinline__ void cp_async16(uint32_t ds, const void* gp) {
    asm volatile("cp.async.cg.shared.global [%0], [%1], 16;" :: "r"(ds), "l"(gp));
}
#define CP_COMMIT() asm volatile("cp.async.commit_group;")
#define CP_WAIT0()  asm volatile("cp.async.wait_group 0;")
#define LDMX4(r0,r1,r2,r3,a) \
    asm volatile("ldmatrix.sync.aligned.m8n8.x4.shared.b16 {%0,%1,%2,%3}, [%4];" \
        : "=r"(r0),"=r"(r1),"=r"(r2),"=r"(r3) : "r"(a))

// ---------------- misc small kernels -----------------------------------------
__global__ void init_slots_kernel(const float* __restrict__ noise,
                                  const float* __restrict__ mean,
                                  const float* __restrict__ logv,
                                  float* __restrict__ slots)
{
    int idx = blockIdx.x * 256 + threadIdx.x;
    int d = idx & 255;
    slots[idx] = mean[d] + expf(logv[d]) * noise[idx];
}

// LN(inputs) fused with bf16 hi/lo split -> g_a2 [M,512]
__device__ __forceinline__ void split4_store(__nv_bfloat16* dst, float4 o) {
    __nv_bfloat16 hx = __float2bfloat16(o.x), hy = __float2bfloat16(o.y);
    __nv_bfloat16 hz = __float2bfloat16(o.z), hw = __float2bfloat16(o.w);
    __nv_bfloat162 h0; h0.x = hx; h0.y = hy;
    __nv_bfloat162 h1; h1.x = hz; h1.y = hw;
    ((__nv_bfloat162*)dst)[0] = h0;
    ((__nv_bfloat162*)dst)[1] = h1;
    __nv_bfloat162 l0, l1;
    l0.x = __float2bfloat16(o.x - __bfloat162float(hx));
    l0.y = __float2bfloat16(o.y - __bfloat162float(hy));
    l1.x = __float2bfloat16(o.z - __bfloat162float(hz));
    l1.y = __float2bfloat16(o.w - __bfloat162float(hw));
    ((__nv_bfloat162*)(dst + 256))[0] = l0;
    ((__nv_bfloat162*)(dst + 256))[1] = l1;
}
__global__ void ln_kv_kernel(const float* __restrict__ src, __nv_bfloat16* __restrict__ dst,
                             const float* __restrict__ w, const float* __restrict__ b)
{
    int row = blockIdx.x * 8 + (threadIdx.x >> 5);
    int lane = threadIdx.x & 31;
    const float4* r4 = (const float4*)(src + (size_t)row * 256);
    float4 v0 = r4[lane], v1 = r4[lane + 32];
    float s  = v0.x + v0.y + v0.z + v0.w + v1.x + v1.y + v1.z + v1.w;
    float sq = v0.x*v0.x + v0.y*v0.y + v0.z*v0.z + v0.w*v0.w
             + v1.x*v1.x + v1.y*v1.y + v1.z*v1.z + v1.w*v1.w;
#pragma unroll
    for (int o = 16; o > 0; o >>= 1) {
        s  += __shfl_xor_sync(~0u, s,  o);
        sq += __shfl_xor_sync(~0u, sq, o);
    }
    float mean = s * (1.0f/256.0f);
    float rstd = rsqrtf(sq * (1.0f/256.0f) - mean*mean + LN_EPSc);
    float4 wa = ((const float4*)w)[lane], wb = ((const float4*)w)[lane+32];
    float4 ba = ((const float4*)b)[lane], bb = ((const float4*)b)[lane+32];
    float4 o0, o1;
    o0.x=(v0.x-mean)*rstd*wa.x+ba.x; o0.y=(v0.y-mean)*rstd*wa.y+ba.y;
    o0.z=(v0.z-mean)*rstd*wa.z+ba.z; o0.w=(v0.w-mean)*rstd*wa.w+ba.w;
    o1.x=(v1.x-mean)*rstd*wb.x+bb.x; o1.y=(v1.y-mean)*rstd*wb.y+bb.y;
    o1.z=(v1.z-mean)*rstd*wb.z+bb.z; o1.w=(v1.w-mean)*rstd*wb.w+bb.w;
    __nv_bfloat16* dr = dst + (size_t)row * 512;
    split4_store(dr + lane*4,       o0);
    split4_store(dr + 128 + lane*4, o1);
}

// W -> [n][k] K-major bf16 hi/lo (n<256: wk, else wv)
__global__ void prep_w_kernel(const float* __restrict__ wk, const float* __restrict__ wv,
                              __nv_bfloat16* __restrict__ B2)
{
    int n = blockIdx.x;          // 0..511
    int k = threadIdx.x;         // 0..255
    const float* W = (n < 256) ? wk : wv;
    float x = W[(size_t)k * 256 + (n & 255)];
    __nv_bfloat16 h = __float2bfloat16(x);
    B2[(size_t)n * 512 + k]       = h;
    B2[(size_t)n * 512 + 256 + k] = __float2bfloat16(x - __bfloat162float(h));
}

// ---------------- K/V GEMM: mma.sync + cp.async double buffer + ldmatrix -----
// Per CTA: D[128m,128n]; 12 K-chunks of 64 (hi/lo compensated, K_eff=768).
// smem/stage: A 16KB + B 16KB, 2 stages = 64KB dynamic. Swizzle: chunk j at j^(r&7).
#define KV_SMEM 65536
__global__ __launch_bounds__(256)
void kv_gemm_mma(const __nv_bfloat16* __restrict__ A2, const __nv_bfloat16* __restrict__ B2,
                 const float* __restrict__ bk, const float* __restrict__ bv,
                 float* __restrict__ Kout, __nv_bfloat16* __restrict__ Vout)
{
    extern __shared__ char dsm[];
    uint32_t sbase = smem_u32(dsm);
    int tid = threadIdx.x, lane = tid & 31, wid = tid >> 5;
    int warp_m = wid & 1, warp_n = wid >> 1;       // 2 x 4 warps
    int cb  = blockIdx.x;                          // 0..3
    int m0  = blockIdx.y * 128;
    int mat = cb >> 1, nh = cb & 1;
    const float* bias = mat ? bv : bk;

    float acc[4][4][4];
#pragma unroll
    for (int a = 0; a < 4; ++a)
#pragma unroll
        for (int b = 0; b < 4; ++b)
#pragma unroll
            for (int r = 0; r < 4; ++r) acc[a][b][r] = 0.0f;

    // per-thread load slots (cp.async): 4 A chunks + 4 B chunks of 16B
    int lr = tid >> 3, lj = tid & 7;               // base row/chunk for i=0
    const int NC = 12;
    int brow_g = mat * 256 + nh * 128;

    auto a_off = [](int c) { return ((c < 8) ? (c & 3) * 64 : 256 + (c & 3) * 64); };
    auto b_off = [](int c) { return ((c < 4) ? c * 64 : (c < 8 ? 256 + (c & 3) * 64 : (c & 3) * 64)); };

    // lane constants for ldmatrix
    int l7 = lane & 7, l15 = lane & 15, lhA = lane >> 4;
    int nrow_loc = (lane >> 4) * 8 + l7, hB = (lane >> 3) & 1;
    uint32_t aRow[4], bRow[2];
#pragma unroll
    for (int mt = 0; mt < 4; ++mt) aRow[mt] = (uint32_t)(warp_m*64 + mt*16 + l15) << 7;
#pragma unroll
    for (int g = 0; g < 2; ++g) bRow[g] = (uint32_t)(warp_n*32 + g*16 + nrow_loc) << 7;

#define LOAD_CHUNK(c, stg) do {                                               \
    uint32_t sa = sbase + (stg)*32768, sb = sa + 16384;                       \
    int ak = a_off(c), bkk = b_off(c);                                        \
    _Pragma("unroll")                                                         \
    for (int i = 0; i < 4; ++i) {                                             \
        int r = lr + i*32;                                                    \
        uint32_t ds = sa + (r<<7) + ((lj ^ (r&7))<<4);                        \
        cp_async16(ds, A2 + (size_t)(m0 + r)*512 + ak + lj*8);                \
    }                                                                         \
    _Pragma("unroll")                                                         \
    for (int i = 0; i < 4; ++i) {                                             \
        int r = lr + i*32;                                                    \
        uint32_t ds = sb + (r<<7) + ((lj ^ (r&7))<<4);                        \
        cp_async16(ds, B2 + (size_t)(brow_g + r)*512 + bkk + lj*8);           \
    }                                                                         \
    CP_COMMIT();                                                              \
} while (0)

    LOAD_CHUNK(0, 0);

    for (int c = 0; c < NC; ++c) {
        CP_WAIT0();
        __syncthreads();
        if (c + 1 < NC) LOAD_CHUNK(c + 1, (c + 1) & 1);
        uint32_t sa = sbase + (c & 1) * 32768, sb = sa + 16384;
#pragma unroll
        for (int ks = 0; ks < 4; ++ks) {
            uint32_t achk = (uint32_t)(((2*ks + lhA) ^ l7) << 4);
            uint32_t bchk = (uint32_t)(((2*ks + hB)  ^ l7) << 4);
            uint32_t af[4][4], bf[2][4];
#pragma unroll
            for (int mt = 0; mt < 4; ++mt)
                LDMX4(af[mt][0], af[mt][1], af[mt][2], af[mt][3], sa + aRow[mt] + achk);
#pragma unroll
            for (int g = 0; g < 2; ++g)
                LDMX4(bf[g][0], bf[g][1], bf[g][2], bf[g][3], sb + bRow[g] + bchk);
#pragma unroll
            for (int mt = 0; mt < 4; ++mt)
#pragma unroll
                for (int nt = 0; nt < 4; ++nt)
                    asm volatile(
                        "mma.sync.aligned.m16n8k16.row.col.f32.bf16.bf16.f32 "
                        "{%0,%1,%2,%3}, {%4,%5,%6,%7}, {%8,%9}, {%0,%1,%2,%3};"
                        : "+f"(acc[mt][nt][0]), "+f"(acc[mt][nt][1]),
                          "+f"(acc[mt][nt][2]), "+f"(acc[mt][nt][3])
                        : "r"(af[mt][0]), "r"(af[mt][1]), "r"(af[mt][2]), "r"(af[mt][3]),
                          "r"(bf[nt>>1][(nt&1)*2]), "r"(bf[nt>>1][(nt&1)*2+1]));
        }
        __syncthreads();
    }

    // epilogue: scatter to [B,H,N,DH]; head h = nh*4 + warp_n
    int col_base = nh * 128 + warp_n * 32;
    int h = col_base >> 5;
#pragma unroll
    for (int mt = 0; mt < 4; ++mt) {
#pragma unroll
        for (int half = 0; half < 2; ++half) {
            int m = m0 + warp_m * 64 + mt * 16 + (lane >> 2) + half * 8;
            int bi = m >> 12, nn = m & 4095;
            size_t base = ((size_t)(bi * 8 + h) * 4096 + nn) * 32;
            if (mat == 0) {
                float* dst = Kout + base;
#pragma unroll
                for (int nt = 0; nt < 4; ++nt) {
                    int dh = nt * 8 + (lane & 3) * 2;
                    float2 o;
                    o.x = acc[mt][nt][half*2+0] + bias[col_base + dh];
                    o.y = acc[mt][nt][half*2+1] + bias[col_base + dh + 1];
                    *(float2*)(dst + dh) = o;
                }
            } else {
                __nv_bfloat16* dst = Vout + base;
#pragma unroll
                for (int nt = 0; nt < 4; ++nt) {
                    int dh = nt * 8 + (lane & 3) * 2;
                    __nv_bfloat162 o;
                    o.x = __float2bfloat16(acc[mt][nt][half*2+0] + bias[col_base + dh]);
                    o.y = __float2bfloat16(acc[mt][nt][half*2+1] + bias[col_base + dh + 1]);
                    *(__nv_bfloat162*)(dst + dh) = o;
                }
            }
        }
    }
#undef LOAD_CHUNK
}

// ---------------- small GEMM (512 rows), optional fused input-LN -------------
// modes: 0 plain, 1 relu, 2 residual add (Ncols=256), 3 q-layout remap
// Batched second GEMM: blocks with blockIdx.y >= y2 run (A2,W2,bias2,out2).
__global__ __launch_bounds__(256)
void gemm512_kernel(const float* __restrict__ Ain, const float* __restrict__ Win,
                    const float* __restrict__ biasin, float* __restrict__ outin,
                    int Ncols, int mode, const float* __restrict__ resid,
                    const float* __restrict__ lnw, const float* __restrict__ lnb,
                    const float* __restrict__ A2, const float* __restrict__ W2,
                    const float* __restrict__ bias2, float* __restrict__ out2,
                    int y2)
{
    __shared__ float As[64][36];
    __shared__ float Bs[64][68];
    __shared__ float s_mean[32], s_rstd[32];
    int tid = threadIdx.x, tx = tid & 31, ty = tid >> 5;
    int c0 = tx*2, r0 = ty*4;
    int m0 = blockIdx.x * 32;
    int yb = blockIdx.y;
    const float* A = Ain; const float* W = Win; const float* bias = biasin;
    float* out = outin;
    if (yb >= y2) { A = A2; W = W2; bias = bias2; out = out2; yb -= y2; }
    int n0 = yb * 64;
    int do_ln = (lnw != nullptr);

    if (do_ln) {
        int r = ty * 4 + (tx >> 3);        // 8 warps x 4 rows
        const float4* rp = (const float4*)(A + (size_t)(m0 + r) * 256);
        float s = 0.0f, sq = 0.0f;
        for (int j = (tx & 7); j < 64; j += 8) {
            float4 v = rp[j];
            s  += v.x + v.y + v.z + v.w;
            sq += v.x*v.x + v.y*v.y + v.z*v.z + v.w*v.w;
        }
#pragma unroll
        for (int o = 4; o > 0; o >>= 1) {
            s  += __shfl_xor_sync(~0u, s,  o);
            sq += __shfl_xor_sync(~0u, sq, o);
        }
        if ((tx & 7) == 0) {
            float mean = s * (1.0f/256.0f);
            s_mean[r] = mean;
            s_rstd[r] = rsqrtf(sq * (1.0f/256.0f) - mean*mean + LN_EPSc);
        }
    }
    __syncthreads();

    float acc[4][2] = {};
    for (int kt = 0; kt < 4; ++kt) {
        __syncthreads();
#pragma unroll
        for (int i = 0; i < 2; ++i) {
            int fid = tid*2 + i, ar = fid >> 4, kq = fid & 15;
            float4 va = *(const float4*)(A + (size_t)(m0+ar)*256 + kt*64 + kq*4);
            if (do_ln) {
                float mn = s_mean[ar], rs = s_rstd[ar];
                float4 lw = *(const float4*)(lnw + kt*64 + kq*4);
                float4 lb = *(const float4*)(lnb + kt*64 + kq*4);
                va.x = (va.x - mn)*rs*lw.x + lb.x;
                va.y = (va.y - mn)*rs*lw.y + lb.y;
                va.z = (va.z - mn)*rs*lw.z + lb.z;
                va.w = (va.w - mn)*rs*lw.w + lb.w;
            }
            As[kq*4+0][ar]=va.x; As[kq*4+1][ar]=va.y; As[kq*4+2][ar]=va.z; As[kq*4+3][ar]=va.w;
        }
#pragma unroll
        for (int j = 0; j < 4; ++j) {
            int fid = tid + j*256, br = fid >> 4, c4 = fid & 15;
            *(float4*)&Bs[br][c4*4] = *(const float4*)(W + (size_t)(kt*64+br)*Ncols + n0 + c4*4);
        }
        __syncthreads();
#pragma unroll 8
        for (int k = 0; k < 64; ++k) {
            float4 a4 = *(const float4*)&As[k][r0];
            float2 b2 = *(const float2*)&Bs[k][c0];
            acc[0][0]+=a4.x*b2.x; acc[0][1]+=a4.x*b2.y;
            acc[1][0]+=a4.y*b2.x; acc[1][1]+=a4.y*b2.y;
            acc[2][0]+=a4.z*b2.x; acc[2][1]+=a4.z*b2.y;
            acc[3][0]+=a4.w*b2.x; acc[3][1]+=a4.w*b2.y;
        }
    }
#pragma unroll
    for (int i = 0; i < 4; ++i)
#pragma unroll
        for (int j = 0; j < 2; ++j) {
            int m = m0 + r0 + i, n = n0 + c0 + j;
            float v = acc[i][j] + bias[n];
            if (mode == 0)      out[(size_t)m*Ncols + n] = v;
            else if (mode == 1) out[(size_t)m*Ncols + n] = fmaxf(v, 0.0f);
            else if (mode == 2) out[(size_t)m*256 + n] = resid[(size_t)m*256 + n] + v;
            else {
                int bq = m >> 3, s = m & 7, h = n >> 5, dh = n & 31;
                out[((size_t)(bq*8 + h)*8 + s)*32 + dh] = v;
            }
        }
}

// ---------------- attention (K fp32, V bf16) ----------------------------------
#define ATT_SMEM ((32768 + 256 + 64 + 2048) * sizeof(float))
__global__ __launch_bounds__(256)
void attention_kernel(const float* __restrict__ q, const float* __restrict__ K,
                      const __nv_bfloat16* __restrict__ Vh, float* __restrict__ upd,
                      float* __restrict__ attn_out, int write_attn)
{
    extern __shared__ float sm[];
    float* attn_s = sm;                    // [8][4096]
    float* q_s    = sm + 32768;            // [8][32]
    float* red    = sm + 32768 + 256;      // [8][8]
    float* red2   = sm + 32768 + 256 + 64; // [8 warps][8 s][32 dh]
    __shared__ float inv_rs[8];
    int bh = blockIdx.x, tid = threadIdx.x;
    int lane = tid & 31, wid = tid >> 5;

    q_s[tid] = q[(size_t)bh*256 + tid] * 0.0625f;  // scale = D^-0.5 = 1/16
    __syncthreads();

    float rs[8] = {};
    const float* Kb = K + (size_t)bh * 4096 * 32;
    for (int it = 0; it < 16; ++it) {
        int n = it*256 + tid;
        const float4* kr = (const float4*)(Kb + (size_t)n * 32);
        float d[8] = {};
#pragma unroll
        for (int c = 0; c < 8; ++c) {
            float4 kk = kr[c];
#pragma unroll
            for (int s = 0; s < 8; ++s) {
                float4 qv = *(const float4*)(q_s + s*32 + c*4);
                d[s] += kk.x*qv.x + kk.y*qv.y + kk.z*qv.z + kk.w*qv.w;
            }
        }
        float mx = d[0];
#pragma unroll
        for (int s = 1; s < 8; ++s) mx = fmaxf(mx, d[s]);
        float e[8], sum = 0.0f;
#pragma unroll
        for (int s = 0; s < 8; ++s) { e[s] = __expf(d[s]-mx); sum += e[s]; }
        float inv = __fdividef(1.0f, sum);
#pragma unroll
        for (int s = 0; s < 8; ++s) {
            float p = e[s]*inv + EPSc;
            attn_s[s*4096 + n] = p;
            rs[s] += p;
        }
    }
#pragma unroll
    for (int s = 0; s < 8; ++s)
#pragma unroll
        for (int o = 16; o > 0; o >>= 1) rs[s] += __shfl_xor_sync(~0u, rs[s], o);
    if (lane == 0)
#pragma unroll
        for (int s = 0; s < 8; ++s) red[wid*8 + s] = rs[s];
    __syncthreads();
    if (tid < 8) {
        float t = 0.0f;
#pragma unroll
        for (int w = 0; w < 8; ++w) t += red[w*8 + tid];
        inv_rs[tid] = 1.0f / fmaxf(t, 1e-12f);
    }

    // pass2: warp w owns n-stripe [w*512, (w+1)*512); V read once per CTA (bf16)
    {
        const __nv_bfloat16* Vb = Vh + (size_t)bh * 4096 * 32;
        float acc[8] = {};
        int nb = wid * 512;
        for (int n = nb; n < nb + 512; n += 4) {
            float4 a[8];
#pragma unroll
            for (int s = 0; s < 8; ++s) a[s] = *(const float4*)(attn_s + s*4096 + n);
            float v0 = __bfloat162float(Vb[(size_t)(n+0)*32 + lane]);
            float v1 = __bfloat162float(Vb[(size_t)(n+1)*32 + lane]);
            float v2 = __bfloat162float(Vb[(size_t)(n+2)*32 + lane]);
            float v3 = __bfloat162float(Vb[(size_t)(n+3)*32 + lane]);
#pragma unroll
            for (int s = 0; s < 8; ++s)
                acc[s] += a[s].x*v0 + a[s].y*v1 + a[s].z*v2 + a[s].w*v3;
        }
#pragma unroll
        for (int s = 0; s < 8; ++s) red2[(wid*8 + s)*32 + lane] = acc[s];
    }
    __syncthreads();
    {
        int s = tid >> 5, dh = tid & 31;
        float t = 0.0f;
#pragma unroll
        for (int w = 0; w < 8; ++w) t += red2[(w*8 + s)*32 + dh];
        int b = bh >> 3, h = bh & 7;
        upd[(size_t)(b*8 + s)*256 + h*32 + dh] = t * inv_rs[s];
    }

    if (write_attn) {
        float* ao = attn_out + (size_t)bh * 32768;
        for (int i = tid; i < 32768; i += 256)
            ao[i] = attn_s[i] * inv_rs[i >> 12];
    }
}

__global__ void gru_combine_kernel(const float* __restrict__ xg,
                                   const float* __restrict__ hg,
                                   float* __restrict__ slots)
{
    int idx = blockIdx.x * 256 + threadIdx.x;
    int row = idx >> 8, c = idx & 255;
    const float* x = xg + (size_t)row * 768;
    const float* h = hg + (size_t)row * 768;
    float r = 1.0f / (1.0f + expf(-(x[c]     + h[c])));
    float z = 1.0f / (1.0f + expf(-(x[256+c] + h[256+c])));
    float n = tanhf(x[512+c] + r * h[512+c]);
    slots[idx] = (1.0f - z) * n + z * slots[idx];
}

// ---------------- launcher ----------------------------------------------------
extern "C" void kernel_launch(void* const* d_in, const int* in_sizes, int n_in,
                              void* d_out, int out_size)
{
    const float* inp   = (const float*)d_in[0];
    const float* noise = (const float*)d_in[1];
    const float* smean = (const float*)d_in[2];
    const float* slogv = (const float*)d_in[3];
    const float* wq = (const float*)d_in[4];  const float* bq = (const float*)d_in[5];
    const float* wk = (const float*)d_in[6];  const float* bk = (const float*)d_in[7];
    const float* wv = (const float*)d_in[8];  const float* bv = (const float*)d_in[9];
    const float* wo = (const float*)d_in[10]; const float* bo = (const float*)d_in[11];
    const float* w_ih = (const float*)d_in[12]; const float* b_ih = (const float*)d_in[13];
    const float* w_hh = (const float*)d_in[14]; const float* b_hh = (const float*)d_in[15];
    const float* w1 = (const float*)d_in[16]; const float* b1 = (const float*)d_in[17];
    const float* w2 = (const float*)d_in[18]; const float* b2 = (const float*)d_in[19];
    const float* lin_w = (const float*)d_in[20]; const float* lin_b = (const float*)d_in[21];
    const float* ls_w  = (const float*)d_in[22]; const float* ls_b  = (const float*)d_in[23];
    const float* lff_w = (const float*)d_in[24]; const float* lff_b = (const float*)d_in[25];

    float* out      = (float*)d_out;
    float* attn_out = out + 131072;

    __nv_bfloat16 *a2, *wb2, *vbh;
    float *kb,*slots,*qb,*upd,*upd2,*h1,*xg,*hg;
    cudaGetSymbolAddress((void**)&a2,   g_a2);
    cudaGetSymbolAddress((void**)&wb2,  g_wb2);
    cudaGetSymbolAddress((void**)&kb,   g_kbuf);
    cudaGetSymbolAddress((void**)&vbh,  g_vbufh);
    cudaGetSymbolAddress((void**)&slots,g_slots);
    cudaGetSymbolAddress((void**)&qb,   g_q);
    cudaGetSymbolAddress((void**)&upd,  g_upd);
    cudaGetSymbolAddress((void**)&upd2, g_upd2);
    cudaGetSymbolAddress((void**)&h1,   g_h1);
    cudaGetSymbolAddress((void**)&xg,   g_xg);
    cudaGetSymbolAddress((void**)&hg,   g_hg);

    cudaFuncSetAttribute(attention_kernel,
                         cudaFuncAttributeMaxDynamicSharedMemorySize, (int)ATT_SMEM);
    cudaFuncSetAttribute(kv_gemm_mma,
                         cudaFuncAttributeMaxDynamicSharedMemorySize, KV_SMEM);

    init_slots_kernel<<<BSc, 256>>>(noise, smean, slogv, slots);
    prep_w_kernel<<<512, 256>>>(wk, wv, wb2);
    ln_kv_kernel<<<Mc/8, 256>>>(inp, a2, lin_w, lin_b);
    kv_gemm_mma<<<dim3(4, Mc/128), 256, KV_SMEM>>>(a2, wb2, bk, bv, kb, vbh);

    for (int it = 0; it < ITERS; ++it) {
        int last = (it == ITERS - 1);
        // q = LN(slots) @ wq  (LN fused), remapped to [B,H,S,DH]
        gemm512_kernel<<<dim3(16, 4), 256>>>(slots, wq, bq, qb, 256, 3, nullptr,
                                             ls_w, ls_b, nullptr, nullptr, nullptr, nullptr, 9999);
        attention_kernel<<<512, 256, ATT_SMEM>>>(qb, kb, vbh, upd, attn_out, last);
        gemm512_kernel<<<dim3(16, 4), 256>>>(upd, wo, bo, upd2, 256, 0, nullptr,
                                             nullptr, nullptr, nullptr, nullptr, nullptr, nullptr, 9999);
        // batched gates: xg = upd2 @ w_ih + b_ih ; hg = slots @ w_hh + b_hh
        gemm512_kernel<<<dim3(16, 24), 256>>>(upd2, w_ih, b_ih, xg, 768, 0, nullptr,
                                              nullptr, nullptr, slots, w_hh, b_hh, hg, 12);
        gru_combine_kernel<<<BSc, 256>>>(xg, hg, slots);
        // ffn1 = relu(LN(slots) @ w1 + b1)  (LN fused)
        gemm512_kernel<<<dim3(16, 4), 256>>>(slots, w1, b1, h1, 256, 1, nullptr,
                                             lff_w, lff_b, nullptr, nullptr, nullptr, nullptr, 9999);
        // ffn2: out = slots + h1 @ w2 + b2
        gemm512_kernel<<<dim3(16, 4), 256>>>(h1, w2, b2, last ? out : slots, 256, 2, slots,
                                             nullptr, nullptr, nullptr, nullptr, nullptr, nullptr, 9999);
    }
}

// round 8
// speedup vs baseline: 2.9243x; 1.4544x over previous
#include <cuda_runtime.h>
#include <cuda_bf16.h>
#include <cstdint>

#define ITERS 3
#define EPSc 1e-8f
#define LN_EPSc 1e-5f
#define Mc 262144   // B*N
#define BSc 512     // B*S

// ---------------- scratch (device globals) ----------------------------------
__device__ __nv_bfloat16 g_a2 [134217728]; // [M,512] = [hi(256) | lo(256)] of LN(x)
__device__ __nv_bfloat16 g_wb2[262144];    // [512 n][512 k] = [hi | lo] K-major
__device__ float         g_kbuf[67108864]; // K [B,H,N,DH] fp32
__device__ __nv_bfloat16 g_vbufh[67108864];// V [B,H,N,DH] bf16
__device__ float g_slots[131072];
__device__ float g_q    [131072];
__device__ float g_upd  [131072];
__device__ float g_upd2 [131072];
__device__ float g_h1   [131072];
__device__ float g_xg   [393216];
__device__ float g_hg   [393216];
__device__ float g_updpart[524288];        // [bh*4+chunk][8s][32dh]
__device__ float g_rspart [16384];         // [bh*4+chunk][8s]
__device__ float g_invrs  [4096];          // [bh][8s]

__device__ __forceinline__ uint32_t smem_u32(const void* p) {
    uint32_t a;
    asm("{ .reg .u64 t; cvta.to.shared.u64 t, %1; cvt.u32.u64 %0, t; }" : "=r"(a) : "l"(p));
    return a;
}
__device__ __forceinline__ void cp_async16(uint32_t ds, const void* gp) {
    asm volatile("cp.async.cg.shared.global [%0], [%1], 16;" :: "r"(ds), "l"(gp));
}
#define CP_COMMIT() asm volatile("cp.async.commit_group;")
#define CP_WAIT1()  asm volatile("cp.async.wait_group 1;")
#define CP_WAIT0()  asm volatile("cp.async.wait_group 0;")
#define LDMX4(r0,r1,r2,r3,a) \
    asm volatile("ldmatrix.sync.aligned.m8n8.x4.shared.b16 {%0,%1,%2,%3}, [%4];" \
        : "=r"(r0),"=r"(r1),"=r"(r2),"=r"(r3) : "r"(a))

// ---------------- misc small kernels -----------------------------------------
__global__ void init_slots_kernel(const float* __restrict__ noise,
                                  const float* __restrict__ mean,
                                  const float* __restrict__ logv,
                                  float* __restrict__ slots)
{
    int idx = blockIdx.x * 256 + threadIdx.x;
    int d = idx & 255;
    slots[idx] = mean[d] + expf(logv[d]) * noise[idx];
}

// LN(inputs) fused with bf16 hi/lo split -> g_a2 [M,512]
__device__ __forceinline__ void split4_store(__nv_bfloat16* dst, float4 o) {
    __nv_bfloat16 hx = __float2bfloat16(o.x), hy = __float2bfloat16(o.y);
    __nv_bfloat16 hz = __float2bfloat16(o.z), hw = __float2bfloat16(o.w);
    __nv_bfloat162 h0; h0.x = hx; h0.y = hy;
    __nv_bfloat162 h1; h1.x = hz; h1.y = hw;
    ((__nv_bfloat162*)dst)[0] = h0;
    ((__nv_bfloat162*)dst)[1] = h1;
    __nv_bfloat162 l0, l1;
    l0.x = __float2bfloat16(o.x - __bfloat162float(hx));
    l0.y = __float2bfloat16(o.y - __bfloat162float(hy));
    l1.x = __float2bfloat16(o.z - __bfloat162float(hz));
    l1.y = __float2bfloat16(o.w - __bfloat162float(hw));
    ((__nv_bfloat162*)(dst + 256))[0] = l0;
    ((__nv_bfloat162*)(dst + 256))[1] = l1;
}
__global__ void ln_kv_kernel(const float* __restrict__ src, __nv_bfloat16* __restrict__ dst,
                             const float* __restrict__ w, const float* __restrict__ b)
{
    int row = blockIdx.x * 8 + (threadIdx.x >> 5);
    int lane = threadIdx.x & 31;
    const float4* r4 = (const float4*)(src + (size_t)row * 256);
    float4 v0 = r4[lane], v1 = r4[lane + 32];
    float s  = v0.x + v0.y + v0.z + v0.w + v1.x + v1.y + v1.z + v1.w;
    float sq = v0.x*v0.x + v0.y*v0.y + v0.z*v0.z + v0.w*v0.w
             + v1.x*v1.x + v1.y*v1.y + v1.z*v1.z + v1.w*v1.w;
#pragma unroll
    for (int o = 16; o > 0; o >>= 1) {
        s  += __shfl_xor_sync(~0u, s,  o);
        sq += __shfl_xor_sync(~0u, sq, o);
    }
    float mean = s * (1.0f/256.0f);
    float rstd = rsqrtf(sq * (1.0f/256.0f) - mean*mean + LN_EPSc);
    float4 wa = ((const float4*)w)[lane], wb = ((const float4*)w)[lane+32];
    float4 ba = ((const float4*)b)[lane], bb = ((const float4*)b)[lane+32];
    float4 o0, o1;
    o0.x=(v0.x-mean)*rstd*wa.x+ba.x; o0.y=(v0.y-mean)*rstd*wa.y+ba.y;
    o0.z=(v0.z-mean)*rstd*wa.z+ba.z; o0.w=(v0.w-mean)*rstd*wa.w+ba.w;
    o1.x=(v1.x-mean)*rstd*wb.x+bb.x; o1.y=(v1.y-mean)*rstd*wb.y+bb.y;
    o1.z=(v1.z-mean)*rstd*wb.z+bb.z; o1.w=(v1.w-mean)*rstd*wb.w+bb.w;
    __nv_bfloat16* dr = dst + (size_t)row * 512;
    split4_store(dr + lane*4,       o0);
    split4_store(dr + 128 + lane*4, o1);
}

// W -> [n][k] K-major bf16 hi/lo (n<256: wk, else wv)
__global__ void prep_w_kernel(const float* __restrict__ wk, const float* __restrict__ wv,
                              __nv_bfloat16* __restrict__ B2)
{
    int n = blockIdx.x;          // 0..511
    int k = threadIdx.x;         // 0..255
    const float* W = (n < 256) ? wk : wv;
    float x = W[(size_t)k * 256 + (n & 255)];
    __nv_bfloat16 h = __float2bfloat16(x);
    B2[(size_t)n * 512 + k]       = h;
    B2[(size_t)n * 512 + 256 + k] = __float2bfloat16(x - __bfloat162float(h));
}

// ---------------- K/V GEMM: mma.sync + 2-deep cp.async pipeline + ldmatrix ---
#define KV_SMEM 65536
__global__ __launch_bounds__(256)
void kv_gemm_mma(const __nv_bfloat16* __restrict__ A2, const __nv_bfloat16* __restrict__ B2,
                 const float* __restrict__ bk, const float* __restrict__ bv,
                 float* __restrict__ Kout, __nv_bfloat16* __restrict__ Vout)
{
    extern __shared__ char dsm[];
    uint32_t sbase = smem_u32(dsm);
    int tid = threadIdx.x, lane = tid & 31, wid = tid >> 5;
    int warp_m = wid & 1, warp_n = wid >> 1;       // 2 x 4 warps
    int cb  = blockIdx.x;                          // 0..3
    int m0  = blockIdx.y * 128;
    int mat = cb >> 1, nh = cb & 1;
    const float* bias = mat ? bv : bk;

    float acc[4][4][4];
#pragma unroll
    for (int a = 0; a < 4; ++a)
#pragma unroll
        for (int b = 0; b < 4; ++b)
#pragma unroll
            for (int r = 0; r < 4; ++r) acc[a][b][r] = 0.0f;

    int lr = tid >> 3, lj = tid & 7;
    const int NC = 12;
    int brow_g = mat * 256 + nh * 128;

    auto a_off = [](int c) { return ((c < 8) ? (c & 3) * 64 : 256 + (c & 3) * 64); };
    auto b_off = [](int c) { return ((c < 4) ? c * 64 : (c < 8 ? 256 + (c & 3) * 64 : (c & 3) * 64)); };

    int l7 = lane & 7, l15 = lane & 15, lhA = lane >> 4;
    int nrow_loc = (lane >> 4) * 8 + l7, hB = (lane >> 3) & 1;
    uint32_t aRow[4], bRow[2];
#pragma unroll
    for (int mt = 0; mt < 4; ++mt) aRow[mt] = (uint32_t)(warp_m*64 + mt*16 + l15) << 7;
#pragma unroll
    for (int g = 0; g < 2; ++g) bRow[g] = (uint32_t)(warp_n*32 + g*16 + nrow_loc) << 7;

#define LOAD_CHUNK(c, stg) do {                                               \
    uint32_t sa = sbase + (stg)*32768, sb = sa + 16384;                       \
    int ak = a_off(c), bkk = b_off(c);                                        \
    _Pragma("unroll")                                                         \
    for (int i = 0; i < 4; ++i) {                                             \
        int r = lr + i*32;                                                    \
        uint32_t ds = sa + (r<<7) + ((lj ^ (r&7))<<4);                        \
        cp_async16(ds, A2 + (size_t)(m0 + r)*512 + ak + lj*8);                \
    }                                                                         \
    _Pragma("unroll")                                                         \
    for (int i = 0; i < 4; ++i) {                                             \
        int r = lr + i*32;                                                    \
        uint32_t ds = sb + (r<<7) + ((lj ^ (r&7))<<4);                        \
        cp_async16(ds, B2 + (size_t)(brow_g + r)*512 + bkk + lj*8);           \
    }                                                                         \
    CP_COMMIT();                                                              \
} while (0)

    LOAD_CHUNK(0, 0);
    LOAD_CHUNK(1, 1);

    for (int c = 0; c < NC; ++c) {
        CP_WAIT1();                 // chunk c resident (c+1 may be in flight)
        __syncthreads();
        uint32_t sa = sbase + (c & 1) * 32768, sb = sa + 16384;
#pragma unroll
        for (int ks = 0; ks < 4; ++ks) {
            uint32_t achk = (uint32_t)(((2*ks + lhA) ^ l7) << 4);
            uint32_t bchk = (uint32_t)(((2*ks + hB)  ^ l7) << 4);
            uint32_t af[4][4], bf[2][4];
#pragma unroll
            for (int mt = 0; mt < 4; ++mt)
                LDMX4(af[mt][0], af[mt][1], af[mt][2], af[mt][3], sa + aRow[mt] + achk);
#pragma unroll
            for (int g = 0; g < 2; ++g)
                LDMX4(bf[g][0], bf[g][1], bf[g][2], bf[g][3], sb + bRow[g] + bchk);
#pragma unroll
            for (int mt = 0; mt < 4; ++mt)
#pragma unroll
                for (int nt = 0; nt < 4; ++nt)
                    asm volatile(
                        "mma.sync.aligned.m16n8k16.row.col.f32.bf16.bf16.f32 "
                        "{%0,%1,%2,%3}, {%4,%5,%6,%7}, {%8,%9}, {%0,%1,%2,%3};"
                        : "+f"(acc[mt][nt][0]), "+f"(acc[mt][nt][1]),
                          "+f"(acc[mt][nt][2]), "+f"(acc[mt][nt][3])
                        : "r"(af[mt][0]), "r"(af[mt][1]), "r"(af[mt][2]), "r"(af[mt][3]),
                          "r"(bf[nt>>1][(nt&1)*2]), "r"(bf[nt>>1][(nt&1)*2+1]));
        }
        __syncthreads();            // everyone done reading stage c&1
        if (c + 2 < NC) LOAD_CHUNK(c + 2, c & 1);
    }

    // epilogue: scatter to [B,H,N,DH]; head h = nh*4 + warp_n
    int col_base = nh * 128 + warp_n * 32;
    int h = col_base >> 5;
#pragma unroll
    for (int mt = 0; mt < 4; ++mt) {
#pragma unroll
        for (int half = 0; half < 2; ++half) {
            int m = m0 + warp_m * 64 + mt * 16 + (lane >> 2) + half * 8;
            int bi = m >> 12, nn = m & 4095;
            size_t base = ((size_t)(bi * 8 + h) * 4096 + nn) * 32;
            if (mat == 0) {
                float* dst = Kout + base;
#pragma unroll
                for (int nt = 0; nt < 4; ++nt) {
                    int dh = nt * 8 + (lane & 3) * 2;
                    float2 o;
                    o.x = acc[mt][nt][half*2+0] + bias[col_base + dh];
                    o.y = acc[mt][nt][half*2+1] + bias[col_base + dh + 1];
                    *(float2*)(dst + dh) = o;
                }
            } else {
                __nv_bfloat16* dst = Vout + base;
#pragma unroll
                for (int nt = 0; nt < 4; ++nt) {
                    int dh = nt * 8 + (lane & 3) * 2;
                    __nv_bfloat162 o;
                    o.x = __float2bfloat16(acc[mt][nt][half*2+0] + bias[col_base + dh]);
                    o.y = __float2bfloat16(acc[mt][nt][half*2+1] + bias[col_base + dh + 1]);
                    *(__nv_bfloat162*)(dst + dh) = o;
                }
            }
        }
    }
#undef LOAD_CHUNK
}

// ---------------- small GEMM (512 rows), optional fused input-LN -------------
__global__ __launch_bounds__(256)
void gemm512_kernel(const float* __restrict__ Ain, const float* __restrict__ Win,
                    const float* __restrict__ biasin, float* __restrict__ outin,
                    int Ncols, int mode, const float* __restrict__ resid,
                    const float* __restrict__ lnw, const float* __restrict__ lnb,
                    const float* __restrict__ A2, const float* __restrict__ W2,
                    const float* __restrict__ bias2, float* __restrict__ out2,
                    int y2)
{
    __shared__ float As[64][36];
    __shared__ float Bs[64][68];
    __shared__ float s_mean[32], s_rstd[32];
    int tid = threadIdx.x, tx = tid & 31, ty = tid >> 5;
    int c0 = tx*2, r0 = ty*4;
    int m0 = blockIdx.x * 32;
    int yb = blockIdx.y;
    const float* A = Ain; const float* W = Win; const float* bias = biasin;
    float* out = outin;
    if (yb >= y2) { A = A2; W = W2; bias = bias2; out = out2; yb -= y2; }
    int n0 = yb * 64;
    int do_ln = (lnw != nullptr);

    if (do_ln) {
        int r = ty * 4 + (tx >> 3);
        const float4* rp = (const float4*)(A + (size_t)(m0 + r) * 256);
        float s = 0.0f, sq = 0.0f;
        for (int j = (tx & 7); j < 64; j += 8) {
            float4 v = rp[j];
            s  += v.x + v.y + v.z + v.w;
            sq += v.x*v.x + v.y*v.y + v.z*v.z + v.w*v.w;
        }
#pragma unroll
        for (int o = 4; o > 0; o >>= 1) {
            s  += __shfl_xor_sync(~0u, s,  o);
            sq += __shfl_xor_sync(~0u, sq, o);
        }
        if ((tx & 7) == 0) {
            float mean = s * (1.0f/256.0f);
            s_mean[r] = mean;
            s_rstd[r] = rsqrtf(sq * (1.0f/256.0f) - mean*mean + LN_EPSc);
        }
    }
    __syncthreads();

    float acc[4][2] = {};
    for (int kt = 0; kt < 4; ++kt) {
        __syncthreads();
#pragma unroll
        for (int i = 0; i < 2; ++i) {
            int fid = tid*2 + i, ar = fid >> 4, kq = fid & 15;
            float4 va = *(const float4*)(A + (size_t)(m0+ar)*256 + kt*64 + kq*4);
            if (do_ln) {
                float mn = s_mean[ar], rs = s_rstd[ar];
                float4 lw = *(const float4*)(lnw + kt*64 + kq*4);
                float4 lb = *(const float4*)(lnb + kt*64 + kq*4);
                va.x = (va.x - mn)*rs*lw.x + lb.x;
                va.y = (va.y - mn)*rs*lw.y + lb.y;
                va.z = (va.z - mn)*rs*lw.z + lb.z;
                va.w = (va.w - mn)*rs*lw.w + lb.w;
            }
            As[kq*4+0][ar]=va.x; As[kq*4+1][ar]=va.y; As[kq*4+2][ar]=va.z; As[kq*4+3][ar]=va.w;
        }
#pragma unroll
        for (int j = 0; j < 4; ++j) {
            int fid = tid + j*256, br = fid >> 4, c4 = fid & 15;
            *(float4*)&Bs[br][c4*4] = *(const float4*)(W + (size_t)(kt*64+br)*Ncols + n0 + c4*4);
        }
        __syncthreads();
#pragma unroll 8
        for (int k = 0; k < 64; ++k) {
            float4 a4 = *(const float4*)&As[k][r0];
            float2 b2 = *(const float2*)&Bs[k][c0];
            acc[0][0]+=a4.x*b2.x; acc[0][1]+=a4.x*b2.y;
            acc[1][0]+=a4.y*b2.x; acc[1][1]+=a4.y*b2.y;
            acc[2][0]+=a4.z*b2.x; acc[2][1]+=a4.z*b2.y;
            acc[3][0]+=a4.w*b2.x; acc[3][1]+=a4.w*b2.y;
        }
    }
#pragma unroll
    for (int i = 0; i < 4; ++i)
#pragma unroll
        for (int j = 0; j < 2; ++j) {
            int m = m0 + r0 + i, n = n0 + c0 + j;
            float v = acc[i][j] + bias[n];
            if (mode == 0)      out[(size_t)m*Ncols + n] = v;
            else if (mode == 1) out[(size_t)m*Ncols + n] = fmaxf(v, 0.0f);
            else if (mode == 2) out[(size_t)m*256 + n] = resid[(size_t)m*256 + n] + v;
            else {
                int bq = m >> 3, s = m & 7, h = n >> 5, dh = n & 31;
                out[((size_t)(bq*8 + h)*8 + s)*32 + dh] = v;
            }
        }
}

// ---------------- attention, n-chunked (4 chunks of 1024) --------------------
#define ATT_SMEM ((8192 + 256 + 64 + 2048) * sizeof(float))
__global__ __launch_bounds__(256)
void attention_part(const float* __restrict__ q, const float* __restrict__ K,
                    const __nv_bfloat16* __restrict__ Vh,
                    float* __restrict__ upd_part, float* __restrict__ rs_part,
                    float* __restrict__ attn_out, int write_attn)
{
    extern __shared__ float sm[];
    float* attn_s = sm;                   // [8][1024]
    float* q_s    = sm + 8192;            // [8][32]
    float* red    = sm + 8192 + 256;      // [8][8]
    float* red2   = sm + 8192 + 256 + 64; // [8 warps][8 s][32 dh]
    int bh = blockIdx.x, chunk = blockIdx.y;
    int tid = threadIdx.x, lane = tid & 31, wid = tid >> 5;
    int n0 = chunk * 1024;

    q_s[tid] = q[(size_t)bh*256 + tid] * 0.0625f;  // scale = D^-0.5 = 1/16
    __syncthreads();

    float rs[8] = {};
    const float* Kb = K + (size_t)bh * 4096 * 32;
    for (int it = 0; it < 4; ++it) {
        int nl = it*256 + tid;
        const float4* kr = (const float4*)(Kb + (size_t)(n0 + nl) * 32);
        float d[8] = {};
#pragma unroll
        for (int c = 0; c < 8; ++c) {
            float4 kk = kr[c];
#pragma unroll
            for (int s = 0; s < 8; ++s) {
                float4 qv = *(const float4*)(q_s + s*32 + c*4);
                d[s] += kk.x*qv.x + kk.y*qv.y + kk.z*qv.z + kk.w*qv.w;
            }
        }
        float mx = d[0];
#pragma unroll
        for (int s = 1; s < 8; ++s) mx = fmaxf(mx, d[s]);
        float e[8], sum = 0.0f;
#pragma unroll
        for (int s = 0; s < 8; ++s) { e[s] = __expf(d[s]-mx); sum += e[s]; }
        float inv = __fdividef(1.0f, sum);
#pragma unroll
        for (int s = 0; s < 8; ++s) {
            float p = e[s]*inv + EPSc;
            attn_s[s*1024 + nl] = p;
            rs[s] += p;
        }
    }
#pragma unroll
    for (int s = 0; s < 8; ++s)
#pragma unroll
        for (int o = 16; o > 0; o >>= 1) rs[s] += __shfl_xor_sync(~0u, rs[s], o);
    if (lane == 0)
#pragma unroll
        for (int s = 0; s < 8; ++s) red[wid*8 + s] = rs[s];
    __syncthreads();
    if (tid < 8) {
        float t = 0.0f;
#pragma unroll
        for (int w = 0; w < 8; ++w) t += red[w*8 + tid];
        rs_part[(size_t)(bh*4 + chunk)*8 + tid] = t;
    }

    // pass2: warp w owns n-substripe [w*128, (w+1)*128) of this chunk
    {
        const __nv_bfloat16* Vb = Vh + (size_t)bh * 4096 * 32;
        float acc[8] = {};
        int nb = wid * 128;
        for (int nl = nb; nl < nb + 128; nl += 4) {
            float4 a[8];
#pragma unroll
            for (int s = 0; s < 8; ++s) a[s] = *(const float4*)(attn_s + s*1024 + nl);
            int n = n0 + nl;
            float v0 = __bfloat162float(Vb[(size_t)(n+0)*32 + lane]);
            float v1 = __bfloat162float(Vb[(size_t)(n+1)*32 + lane]);
            float v2 = __bfloat162float(Vb[(size_t)(n+2)*32 + lane]);
            float v3 = __bfloat162float(Vb[(size_t)(n+3)*32 + lane]);
#pragma unroll
            for (int s = 0; s < 8; ++s)
                acc[s] += a[s].x*v0 + a[s].y*v1 + a[s].z*v2 + a[s].w*v3;
        }
#pragma unroll
        for (int s = 0; s < 8; ++s) red2[(wid*8 + s)*32 + lane] = acc[s];
    }
    __syncthreads();
    if (tid < 256) {
        int s = tid >> 5, dh = tid & 31;
        float t = 0.0f;
#pragma unroll
        for (int w = 0; w < 8; ++w) t += red2[(w*8 + s)*32 + dh];
        upd_part[(size_t)(bh*4 + chunk)*256 + s*32 + dh] = t;
    }

    if (write_attn) {  // unnormalized p; scaled later by attn_scale
        float* ao = attn_out + (size_t)bh * 32768 + n0;
        for (int i = tid; i < 8192; i += 256)
            ao[(i >> 10) * 4096 + (i & 1023)] = attn_s[i];
    }
}

__global__ void attn_finalize(const float* __restrict__ upd_part,
                              const float* __restrict__ rs_part,
                              float* __restrict__ upd, float* __restrict__ invrs)
{
    int bh = blockIdx.x, tid = threadIdx.x;
    __shared__ float inv[8];
    if (tid < 8) {
        float t = 0.0f;
#pragma unroll
        for (int c = 0; c < 4; ++c) t += rs_part[(size_t)(bh*4 + c)*8 + tid];
        float v = 1.0f / fmaxf(t, 1e-12f);
        inv[tid] = v;
        invrs[bh*8 + tid] = v;
    }
    __syncthreads();
    int s = tid >> 5, dh = tid & 31;
    float t = 0.0f;
#pragma unroll
    for (int c = 0; c < 4; ++c) t += upd_part[(size_t)(bh*4 + c)*256 + s*32 + dh];
    int b = bh >> 3, h = bh & 7;
    upd[(size_t)(b*8 + s)*256 + h*32 + dh] = t * inv[s];
}

__global__ void attn_scale(float* __restrict__ ao, const float* __restrict__ invrs)
{
    int bh = blockIdx.x, tid = threadIdx.x;
    __shared__ float inv[8];
    if (tid < 8) inv[tid] = invrs[bh*8 + tid];
    __syncthreads();
    float* p = ao + (size_t)bh * 32768;
    for (int i = tid; i < 32768; i += 256)
        p[i] *= inv[i >> 12];
}

__global__ void gru_combine_kernel(const float* __restrict__ xg,
                                   const float* __restrict__ hg,
                                   float* __restrict__ slots)
{
    int idx = blockIdx.x * 256 + threadIdx.x;
    int row = idx >> 8, c = idx & 255;
    const float* x = xg + (size_t)row * 768;
    const float* h = hg + (size_t)row * 768;
    float r = 1.0f / (1.0f + expf(-(x[c]     + h[c])));
    float z = 1.0f / (1.0f + expf(-(x[256+c] + h[256+c])));
    float n = tanhf(x[512+c] + r * h[512+c]);
    slots[idx] = (1.0f - z) * n + z * slots[idx];
}

// ---------------- launcher ----------------------------------------------------
extern "C" void kernel_launch(void* const* d_in, const int* in_sizes, int n_in,
                              void* d_out, int out_size)
{
    const float* inp   = (const float*)d_in[0];
    const float* noise = (const float*)d_in[1];
    const float* smean = (const float*)d_in[2];
    const float* slogv = (const float*)d_in[3];
    const float* wq = (const float*)d_in[4];  const float* bq = (const float*)d_in[5];
    const float* wk = (const float*)d_in[6];  const float* bk = (const float*)d_in[7];
    const float* wv = (const float*)d_in[8];  const float* bv = (const float*)d_in[9];
    const float* wo = (const float*)d_in[10]; const float* bo = (const float*)d_in[11];
    const float* w_ih = (const float*)d_in[12]; const float* b_ih = (const float*)d_in[13];
    const float* w_hh = (const float*)d_in[14]; const float* b_hh = (const float*)d_in[15];
    const float* w1 = (const float*)d_in[16]; const float* b1 = (const float*)d_in[17];
    const float* w2 = (const float*)d_in[18]; const float* b2 = (const float*)d_in[19];
    const float* lin_w = (const float*)d_in[20]; const float* lin_b = (const float*)d_in[21];
    const float* ls_w  = (const float*)d_in[22]; const float* ls_b  = (const float*)d_in[23];
    const float* lff_w = (const float*)d_in[24]; const float* lff_b = (const float*)d_in[25];

    float* out      = (float*)d_out;
    float* attn_out = out + 131072;

    __nv_bfloat16 *a2, *wb2, *vbh;
    float *kb,*slots,*qb,*upd,*upd2,*h1,*xg,*hg,*updp,*rsp,*invr;
    cudaGetSymbolAddress((void**)&a2,   g_a2);
    cudaGetSymbolAddress((void**)&wb2,  g_wb2);
    cudaGetSymbolAddress((void**)&kb,   g_kbuf);
    cudaGetSymbolAddress((void**)&vbh,  g_vbufh);
    cudaGetSymbolAddress((void**)&slots,g_slots);
    cudaGetSymbolAddress((void**)&qb,   g_q);
    cudaGetSymbolAddress((void**)&upd,  g_upd);
    cudaGetSymbolAddress((void**)&upd2, g_upd2);
    cudaGetSymbolAddress((void**)&h1,   g_h1);
    cudaGetSymbolAddress((void**)&xg,   g_xg);
    cudaGetSymbolAddress((void**)&hg,   g_hg);
    cudaGetSymbolAddress((void**)&updp, g_updpart);
    cudaGetSymbolAddress((void**)&rsp,  g_rspart);
    cudaGetSymbolAddress((void**)&invr, g_invrs);

    cudaFuncSetAttribute(attention_part,
                         cudaFuncAttributeMaxDynamicSharedMemorySize, (int)ATT_SMEM);
    cudaFuncSetAttribute(kv_gemm_mma,
                         cudaFuncAttributeMaxDynamicSharedMemorySize, KV_SMEM);

    init_slots_kernel<<<BSc, 256>>>(noise, smean, slogv, slots);
    prep_w_kernel<<<512, 256>>>(wk, wv, wb2);
    ln_kv_kernel<<<Mc/8, 256>>>(inp, a2, lin_w, lin_b);
    kv_gemm_mma<<<dim3(4, Mc/128), 256, KV_SMEM>>>(a2, wb2, bk, bv, kb, vbh);

    for (int it = 0; it < ITERS; ++it) {
        int last = (it == ITERS - 1);
        gemm512_kernel<<<dim3(16, 4), 256>>>(slots, wq, bq, qb, 256, 3, nullptr,
                                             ls_w, ls_b, nullptr, nullptr, nullptr, nullptr, 9999);
        attention_part<<<dim3(512, 4), 256, ATT_SMEM>>>(qb, kb, vbh, updp, rsp, attn_out, last);
        attn_finalize<<<512, 256>>>(updp, rsp, upd, invr);
        if (last) attn_scale<<<512, 256>>>(attn_out, invr);
        gemm512_kernel<<<dim3(16, 4), 256>>>(upd, wo, bo, upd2, 256, 0, nullptr,
                                             nullptr, nullptr, nullptr, nullptr, nullptr, nullptr, 9999);
        gemm512_kernel<<<dim3(16, 24), 256>>>(upd2, w_ih, b_ih, xg, 768, 0, nullptr,
                                              nullptr, nullptr, slots, w_hh, b_hh, hg, 12);
        gru_combine_kernel<<<BSc, 256>>>(xg, hg, slots);
        gemm512_kernel<<<dim3(16, 4), 256>>>(slots, w1, b1, h1, 256, 1, nullptr,
                                             lff_w, lff_b, nullptr, nullptr, nullptr, nullptr, 9999);
        gemm512_kernel<<<dim3(16, 4), 256>>>(h1, w2, b2, last ? out : slots, 256, 2, slots,
                                             nullptr, nullptr, nullptr, nullptr, nullptr, nullptr, 9999);
    }
}

// round 9
// speedup vs baseline: 3.3583x; 1.1484x over previous
#include <cuda_runtime.h>
#include <cuda_bf16.h>
#include <cstdint>

#define ITERS 3
#define EPSc 1e-8f
#define LN_EPSc 1e-5f
#define Mc 262144   // B*N
#define BSc 512     // B*S

// ---------------- scratch (device globals) ----------------------------------
__device__ __nv_bfloat16 g_a2 [134217728]; // [M,512] = [hi(256) | lo(256)] of LN(x)
__device__ __nv_bfloat16 g_wb2[262144];    // [512 n][512 k] = [hi | lo] K-major
__device__ __nv_bfloat16 g_kbufh[67108864];// K [B,H,N,DH] bf16
__device__ __nv_bfloat16 g_vbufh[67108864];// V [B,H,N,DH] bf16
__device__ float g_slots[131072];
__device__ float g_q    [131072];
__device__ float g_upd  [131072];
__device__ float g_upd2 [131072];
__device__ float g_h1   [131072];
__device__ float g_xg   [393216];
__device__ float g_hg   [393216];
__device__ float g_updpart[524288];        // [bh*4+chunk][8s][32dh]
__device__ float g_rspart [16384];         // [bh*4+chunk][8s]
__device__ float g_invrs  [4096];          // [bh][8s]

__device__ __forceinline__ uint32_t smem_u32(const void* p) {
    uint32_t a;
    asm("{ .reg .u64 t; cvta.to.shared.u64 t, %1; cvt.u32.u64 %0, t; }" : "=r"(a) : "l"(p));
    return a;
}
__device__ __forceinline__ void cp_async16(uint32_t ds, const void* gp) {
    asm volatile("cp.async.cg.shared.global [%0], [%1], 16;" :: "r"(ds), "l"(gp));
}
#define CP_COMMIT() asm volatile("cp.async.commit_group;")
#define CP_WAIT1()  asm volatile("cp.async.wait_group 1;")
#define LDMX4(r0,r1,r2,r3,a) \
    asm volatile("ldmatrix.sync.aligned.m8n8.x4.shared.b16 {%0,%1,%2,%3}, [%4];" \
        : "=r"(r0),"=r"(r1),"=r"(r2),"=r"(r3) : "r"(a))
#define MMA16816(acc, a0,a1,a2,a3, b0,b1) \
    asm volatile("mma.sync.aligned.m16n8k16.row.col.f32.bf16.bf16.f32 " \
        "{%0,%1,%2,%3}, {%4,%5,%6,%7}, {%8,%9}, {%0,%1,%2,%3};" \
        : "+f"((acc)[0]), "+f"((acc)[1]), "+f"((acc)[2]), "+f"((acc)[3]) \
        : "r"(a0), "r"(a1), "r"(a2), "r"(a3), "r"(b0), "r"(b1))

// ---------------- misc small kernels -----------------------------------------
__global__ void init_slots_kernel(const float* __restrict__ noise,
                                  const float* __restrict__ mean,
                                  const float* __restrict__ logv,
                                  float* __restrict__ slots)
{
    int idx = blockIdx.x * 256 + threadIdx.x;
    int d = idx & 255;
    slots[idx] = mean[d] + expf(logv[d]) * noise[idx];
}

// LN(inputs) fused with bf16 hi/lo split -> g_a2 [M,512]
__device__ __forceinline__ void split4_store(__nv_bfloat16* dst, float4 o) {
    __nv_bfloat16 hx = __float2bfloat16(o.x), hy = __float2bfloat16(o.y);
    __nv_bfloat16 hz = __float2bfloat16(o.z), hw = __float2bfloat16(o.w);
    __nv_bfloat162 h0; h0.x = hx; h0.y = hy;
    __nv_bfloat162 h1; h1.x = hz; h1.y = hw;
    ((__nv_bfloat162*)dst)[0] = h0;
    ((__nv_bfloat162*)dst)[1] = h1;
    __nv_bfloat162 l0, l1;
    l0.x = __float2bfloat16(o.x - __bfloat162float(hx));
    l0.y = __float2bfloat16(o.y - __bfloat162float(hy));
    l1.x = __float2bfloat16(o.z - __bfloat162float(hz));
    l1.y = __float2bfloat16(o.w - __bfloat162float(hw));
    ((__nv_bfloat162*)(dst + 256))[0] = l0;
    ((__nv_bfloat162*)(dst + 256))[1] = l1;
}
__global__ void ln_kv_kernel(const float* __restrict__ src, __nv_bfloat16* __restrict__ dst,
                             const float* __restrict__ w, const float* __restrict__ b)
{
    int row = blockIdx.x * 8 + (threadIdx.x >> 5);
    int lane = threadIdx.x & 31;
    const float4* r4 = (const float4*)(src + (size_t)row * 256);
    float4 v0 = r4[lane], v1 = r4[lane + 32];
    float s  = v0.x + v0.y + v0.z + v0.w + v1.x + v1.y + v1.z + v1.w;
    float sq = v0.x*v0.x + v0.y*v0.y + v0.z*v0.z + v0.w*v0.w
             + v1.x*v1.x + v1.y*v1.y + v1.z*v1.z + v1.w*v1.w;
#pragma unroll
    for (int o = 16; o > 0; o >>= 1) {
        s  += __shfl_xor_sync(~0u, s,  o);
        sq += __shfl_xor_sync(~0u, sq, o);
    }
    float mean = s * (1.0f/256.0f);
    float rstd = rsqrtf(sq * (1.0f/256.0f) - mean*mean + LN_EPSc);
    float4 wa = ((const float4*)w)[lane], wb = ((const float4*)w)[lane+32];
    float4 ba = ((const float4*)b)[lane], bb = ((const float4*)b)[lane+32];
    float4 o0, o1;
    o0.x=(v0.x-mean)*rstd*wa.x+ba.x; o0.y=(v0.y-mean)*rstd*wa.y+ba.y;
    o0.z=(v0.z-mean)*rstd*wa.z+ba.z; o0.w=(v0.w-mean)*rstd*wa.w+ba.w;
    o1.x=(v1.x-mean)*rstd*wb.x+bb.x; o1.y=(v1.y-mean)*rstd*wb.y+bb.y;
    o1.z=(v1.z-mean)*rstd*wb.z+bb.z; o1.w=(v1.w-mean)*rstd*wb.w+bb.w;
    __nv_bfloat16* dr = dst + (size_t)row * 512;
    split4_store(dr + lane*4,       o0);
    split4_store(dr + 128 + lane*4, o1);
}

// W -> [n][k] K-major bf16 hi/lo (n<256: wk, else wv)
__global__ void prep_w_kernel(const float* __restrict__ wk, const float* __restrict__ wv,
                              __nv_bfloat16* __restrict__ B2)
{
    int n = blockIdx.x;          // 0..511
    int k = threadIdx.x;         // 0..255
    const float* W = (n < 256) ? wk : wv;
    float x = W[(size_t)k * 256 + (n & 255)];
    __nv_bfloat16 h = __float2bfloat16(x);
    B2[(size_t)n * 512 + k]       = h;
    B2[(size_t)n * 512 + 256 + k] = __float2bfloat16(x - __bfloat162float(h));
}

// ---------------- K/V GEMM: 8-chunk schedule, A-frag reuse over B-hi/B-lo ----
// stage = [A 16K | B-hi 16K | B-lo 16K] = 48 KB; 2 stages = 96 KB.
// chunks 0-3: A-hi(c*64) vs B-hi(c*64) AND B-lo(256+c*64)   (32 MMA/ks)
// chunks 4-7: A-lo(256+(c-4)*64) vs B-hi((c-4)*64)          (16 MMA/ks)
#define KV_SMEM (49152 * 2)
__global__ __launch_bounds__(256, 2)
void kv_gemm_mma(const __nv_bfloat16* __restrict__ A2, const __nv_bfloat16* __restrict__ B2,
                 const float* __restrict__ bk, const float* __restrict__ bv,
                 __nv_bfloat16* __restrict__ Kout, __nv_bfloat16* __restrict__ Vout)
{
    extern __shared__ char dsm[];
    uint32_t sbase = smem_u32(dsm);
    int tid = threadIdx.x, lane = tid & 31, wid = tid >> 5;
    int warp_m = wid & 1, warp_n = wid >> 1;       // 2 x 4 warps
    int cb  = blockIdx.x;                          // 0..3
    int m0  = blockIdx.y * 128;
    int mat = cb >> 1, nh = cb & 1;
    const float* bias = mat ? bv : bk;
    __nv_bfloat16* Out = mat ? Vout : Kout;

    float acc[4][4][4];
#pragma unroll
    for (int a = 0; a < 4; ++a)
#pragma unroll
        for (int b = 0; b < 4; ++b)
#pragma unroll
            for (int r = 0; r < 4; ++r) acc[a][b][r] = 0.0f;

    int lr = tid >> 3, lj = tid & 7;
    int brow_g = mat * 256 + nh * 128;

    int l7 = lane & 7, l15 = lane & 15, lhA = lane >> 4;
    int nrow_loc = (lane >> 4) * 8 + l7, hB = (lane >> 3) & 1;
    uint32_t aRow[4], bRow[2];
#pragma unroll
    for (int mt = 0; mt < 4; ++mt) aRow[mt] = (uint32_t)(warp_m*64 + mt*16 + l15) << 7;
#pragma unroll
    for (int g = 0; g < 2; ++g) bRow[g] = (uint32_t)(warp_n*32 + g*16 + nrow_loc) << 7;

#define LOAD_CHUNK(c, stg) do {                                               \
    uint32_t sa = sbase + (stg)*49152;                                        \
    int cc = (c);                                                             \
    int ak = (cc < 4) ? cc*64 : 256 + (cc-4)*64;                              \
    int b0 = (cc < 4) ? cc*64 : (cc-4)*64;                                    \
    _Pragma("unroll")                                                         \
    for (int i = 0; i < 4; ++i) {                                             \
        int r = lr + i*32;                                                    \
        uint32_t so = (r<<7) + ((lj ^ (r&7))<<4);                             \
        cp_async16(sa + so, A2 + (size_t)(m0 + r)*512 + ak + lj*8);           \
        cp_async16(sa + 16384 + so, B2 + (size_t)(brow_g + r)*512 + b0 + lj*8);\
    }                                                                         \
    if (cc < 4) {                                                             \
        int b1 = 256 + cc*64;                                                 \
        _Pragma("unroll")                                                     \
        for (int i = 0; i < 4; ++i) {                                         \
            int r = lr + i*32;                                                \
            uint32_t so = (r<<7) + ((lj ^ (r&7))<<4);                         \
            cp_async16(sa + 32768 + so, B2 + (size_t)(brow_g + r)*512 + b1 + lj*8);\
        }                                                                     \
    }                                                                         \
    CP_COMMIT();                                                              \
} while (0)

    LOAD_CHUNK(0, 0);
    LOAD_CHUNK(1, 1);

    for (int c = 0; c < 8; ++c) {
        CP_WAIT1();
        __syncthreads();
        uint32_t sa = sbase + (c & 1) * 49152;
#pragma unroll
        for (int ks = 0; ks < 4; ++ks) {
            uint32_t achk = (uint32_t)(((2*ks + lhA) ^ l7) << 4);
            uint32_t bchk = (uint32_t)(((2*ks + hB)  ^ l7) << 4);
            uint32_t af[4][4];
#pragma unroll
            for (int mt = 0; mt < 4; ++mt)
                LDMX4(af[mt][0], af[mt][1], af[mt][2], af[mt][3], sa + aRow[mt] + achk);
            {   // B-hi product
                uint32_t bf[2][4];
#pragma unroll
                for (int g = 0; g < 2; ++g)
                    LDMX4(bf[g][0], bf[g][1], bf[g][2], bf[g][3], sa + 16384 + bRow[g] + bchk);
#pragma unroll
                for (int mt = 0; mt < 4; ++mt)
#pragma unroll
                    for (int nt = 0; nt < 4; ++nt)
                        MMA16816(acc[mt][nt], af[mt][0], af[mt][1], af[mt][2], af[mt][3],
                                 bf[nt>>1][(nt&1)*2], bf[nt>>1][(nt&1)*2+1]);
            }
            if (c < 4) {  // B-lo product (same A fragments)
                uint32_t bf[2][4];
#pragma unroll
                for (int g = 0; g < 2; ++g)
                    LDMX4(bf[g][0], bf[g][1], bf[g][2], bf[g][3], sa + 32768 + bRow[g] + bchk);
#pragma unroll
                for (int mt = 0; mt < 4; ++mt)
#pragma unroll
                    for (int nt = 0; nt < 4; ++nt)
                        MMA16816(acc[mt][nt], af[mt][0], af[mt][1], af[mt][2], af[mt][3],
                                 bf[nt>>1][(nt&1)*2], bf[nt>>1][(nt&1)*2+1]);
            }
        }
        __syncthreads();
        if (c + 2 < 8) LOAD_CHUNK(c + 2, c & 1);
    }

    // epilogue: scatter bf16 to [B,H,N,DH]; head h = nh*4 + warp_n
    int col_base = nh * 128 + warp_n * 32;
    int h = col_base >> 5;
#pragma unroll
    for (int mt = 0; mt < 4; ++mt) {
#pragma unroll
        for (int half = 0; half < 2; ++half) {
            int m = m0 + warp_m * 64 + mt * 16 + (lane >> 2) + half * 8;
            int bi = m >> 12, nn = m & 4095;
            __nv_bfloat16* dst = Out + ((size_t)(bi * 8 + h) * 4096 + nn) * 32;
#pragma unroll
            for (int nt = 0; nt < 4; ++nt) {
                int dh = nt * 8 + (lane & 3) * 2;
                __nv_bfloat162 o;
                o.x = __float2bfloat16(acc[mt][nt][half*2+0] + bias[col_base + dh]);
                o.y = __float2bfloat16(acc[mt][nt][half*2+1] + bias[col_base + dh + 1]);
                *(__nv_bfloat162*)(dst + dh) = o;
            }
        }
    }
#undef LOAD_CHUNK
}

// ---------------- small GEMM (512 rows), optional fused input-LN -------------
__global__ __launch_bounds__(256)
void gemm512_kernel(const float* __restrict__ Ain, const float* __restrict__ Win,
                    const float* __restrict__ biasin, float* __restrict__ outin,
                    int Ncols, int mode, const float* __restrict__ resid,
                    const float* __restrict__ lnw, const float* __restrict__ lnb,
                    const float* __restrict__ A2, const float* __restrict__ W2,
                    const float* __restrict__ bias2, float* __restrict__ out2,
                    int y2)
{
    __shared__ float As[64][36];
    __shared__ float Bs[64][68];
    __shared__ float s_mean[32], s_rstd[32];
    int tid = threadIdx.x, tx = tid & 31, ty = tid >> 5;
    int c0 = tx*2, r0 = ty*4;
    int m0 = blockIdx.x * 32;
    int yb = blockIdx.y;
    const float* A = Ain; const float* W = Win; const float* bias = biasin;
    float* out = outin;
    if (yb >= y2) { A = A2; W = W2; bias = bias2; out = out2; yb -= y2; }
    int n0 = yb * 64;
    int do_ln = (lnw != nullptr);

    if (do_ln) {
        int r = ty * 4 + (tx >> 3);
        const float4* rp = (const float4*)(A + (size_t)(m0 + r) * 256);
        float s = 0.0f, sq = 0.0f;
        for (int j = (tx & 7); j < 64; j += 8) {
            float4 v = rp[j];
            s  += v.x + v.y + v.z + v.w;
            sq += v.x*v.x + v.y*v.y + v.z*v.z + v.w*v.w;
        }
#pragma unroll
        for (int o = 4; o > 0; o >>= 1) {
            s  += __shfl_xor_sync(~0u, s,  o);
            sq += __shfl_xor_sync(~0u, sq, o);
        }
        if ((tx & 7) == 0) {
            float mean = s * (1.0f/256.0f);
            s_mean[r] = mean;
            s_rstd[r] = rsqrtf(sq * (1.0f/256.0f) - mean*mean + LN_EPSc);
        }
    }
    __syncthreads();

    float acc[4][2] = {};
    for (int kt = 0; kt < 4; ++kt) {
        __syncthreads();
#pragma unroll
        for (int i = 0; i < 2; ++i) {
            int fid = tid*2 + i, ar = fid >> 4, kq = fid & 15;
            float4 va = *(const float4*)(A + (size_t)(m0+ar)*256 + kt*64 + kq*4);
            if (do_ln) {
                float mn = s_mean[ar], rs = s_rstd[ar];
                float4 lw = *(const float4*)(lnw + kt*64 + kq*4);
                float4 lb = *(const float4*)(lnb + kt*64 + kq*4);
                va.x = (va.x - mn)*rs*lw.x + lb.x;
                va.y = (va.y - mn)*rs*lw.y + lb.y;
                va.z = (va.z - mn)*rs*lw.z + lb.z;
                va.w = (va.w - mn)*rs*lw.w + lb.w;
            }
            As[kq*4+0][ar]=va.x; As[kq*4+1][ar]=va.y; As[kq*4+2][ar]=va.z; As[kq*4+3][ar]=va.w;
        }
#pragma unroll
        for (int j = 0; j < 4; ++j) {
            int fid = tid + j*256, br = fid >> 4, c4 = fid & 15;
            *(float4*)&Bs[br][c4*4] = *(const float4*)(W + (size_t)(kt*64+br)*Ncols + n0 + c4*4);
        }
        __syncthreads();
#pragma unroll 8
        for (int k = 0; k < 64; ++k) {
            float4 a4 = *(const float4*)&As[k][r0];
            float2 b2 = *(const float2*)&Bs[k][c0];
            acc[0][0]+=a4.x*b2.x; acc[0][1]+=a4.x*b2.y;
            acc[1][0]+=a4.y*b2.x; acc[1][1]+=a4.y*b2.y;
            acc[2][0]+=a4.z*b2.x; acc[2][1]+=a4.z*b2.y;
            acc[3][0]+=a4.w*b2.x; acc[3][1]+=a4.w*b2.y;
        }
    }
#pragma unroll
    for (int i = 0; i < 4; ++i)
#pragma unroll
        for (int j = 0; j < 2; ++j) {
            int m = m0 + r0 + i, n = n0 + c0 + j;
            float v = acc[i][j] + bias[n];
            if (mode == 0)      out[(size_t)m*Ncols + n] = v;
            else if (mode == 1) out[(size_t)m*Ncols + n] = fmaxf(v, 0.0f);
            else if (mode == 2) out[(size_t)m*256 + n] = resid[(size_t)m*256 + n] + v;
            else {
                int bq = m >> 3, s = m & 7, h = n >> 5, dh = n & 31;
                out[((size_t)(bq*8 + h)*8 + s)*32 + dh] = v;
            }
        }
}

// ---------------- attention, n-chunked (4 chunks of 1024), K+V bf16 ----------
#define ATT_SMEM ((8192 + 256 + 64 + 2048) * sizeof(float))
__global__ __launch_bounds__(256)
void attention_part(const float* __restrict__ q, const __nv_bfloat16* __restrict__ Kh,
                    const __nv_bfloat16* __restrict__ Vh,
                    float* __restrict__ upd_part, float* __restrict__ rs_part,
                    float* __restrict__ attn_out, int write_attn)
{
    extern __shared__ float sm[];
    float* attn_s = sm;                   // [8][1024]
    float* q_s    = sm + 8192;            // [8][32]
    float* red    = sm + 8192 + 256;      // [8][8]
    float* red2   = sm + 8192 + 256 + 64; // [8 warps][8 s][32 dh]
    int bh = blockIdx.x, chunk = blockIdx.y;
    int tid = threadIdx.x, lane = tid & 31, wid = tid >> 5;
    int n0 = chunk * 1024;

    q_s[tid] = q[(size_t)bh*256 + tid] * 0.0625f;  // scale = D^-0.5 = 1/16
    __syncthreads();

    float rs[8] = {};
    const __nv_bfloat16* Kb = Kh + (size_t)bh * 4096 * 32;
    for (int it = 0; it < 4; ++it) {
        int nl = it*256 + tid;
        const __nv_bfloat16* kr = Kb + (size_t)(n0 + nl) * 32;
        float d[8] = {};
#pragma unroll
        for (int c4 = 0; c4 < 4; ++c4) {
            float4 raw = *(const float4*)(kr + c4*8);
            const __nv_bfloat162* kp = (const __nv_bfloat162*)&raw;
            float2 k0 = __bfloat1622float2(kp[0]);
            float2 k1 = __bfloat1622float2(kp[1]);
            float2 k2 = __bfloat1622float2(kp[2]);
            float2 k3 = __bfloat1622float2(kp[3]);
#pragma unroll
            for (int s = 0; s < 8; ++s) {
                float4 qa = *(const float4*)(q_s + s*32 + c4*8);
                float4 qb = *(const float4*)(q_s + s*32 + c4*8 + 4);
                d[s] += k0.x*qa.x + k0.y*qa.y + k1.x*qa.z + k1.y*qa.w
                      + k2.x*qb.x + k2.y*qb.y + k3.x*qb.z + k3.y*qb.w;
            }
        }
        float mx = d[0];
#pragma unroll
        for (int s = 1; s < 8; ++s) mx = fmaxf(mx, d[s]);
        float e[8], sum = 0.0f;
#pragma unroll
        for (int s = 0; s < 8; ++s) { e[s] = __expf(d[s]-mx); sum += e[s]; }
        float inv = __fdividef(1.0f, sum);
#pragma unroll
        for (int s = 0; s < 8; ++s) {
            float p = e[s]*inv + EPSc;
            attn_s[s*1024 + nl] = p;
            rs[s] += p;
        }
    }
#pragma unroll
    for (int s = 0; s < 8; ++s)
#pragma unroll
        for (int o = 16; o > 0; o >>= 1) rs[s] += __shfl_xor_sync(~0u, rs[s], o);
    if (lane == 0)
#pragma unroll
        for (int s = 0; s < 8; ++s) red[wid*8 + s] = rs[s];
    __syncthreads();
    if (tid < 8) {
        float t = 0.0f;
#pragma unroll
        for (int w = 0; w < 8; ++w) t += red[w*8 + tid];
        rs_part[(size_t)(bh*4 + chunk)*8 + tid] = t;
    }

    // pass2: warp w owns n-substripe [w*128, (w+1)*128) of this chunk
    {
        const __nv_bfloat16* Vb = Vh + (size_t)bh * 4096 * 32;
        float acc[8] = {};
        int nb = wid * 128;
        for (int nl = nb; nl < nb + 128; nl += 4) {
            float4 a[8];
#pragma unroll
            for (int s = 0; s < 8; ++s) a[s] = *(const float4*)(attn_s + s*1024 + nl);
            int n = n0 + nl;
            float v0 = __bfloat162float(Vb[(size_t)(n+0)*32 + lane]);
            float v1 = __bfloat162float(Vb[(size_t)(n+1)*32 + lane]);
            float v2 = __bfloat162float(Vb[(size_t)(n+2)*32 + lane]);
            float v3 = __bfloat162float(Vb[(size_t)(n+3)*32 + lane]);
#pragma unroll
            for (int s = 0; s < 8; ++s)
                acc[s] += a[s].x*v0 + a[s].y*v1 + a[s].z*v2 + a[s].w*v3;
        }
#pragma unroll
        for (int s = 0; s < 8; ++s) red2[(wid*8 + s)*32 + lane] = acc[s];
    }
    __syncthreads();
    {
        int s = tid >> 5, dh = tid & 31;
        float t = 0.0f;
#pragma unroll
        for (int w = 0; w < 8; ++w) t += red2[(w*8 + s)*32 + dh];
        upd_part[(size_t)(bh*4 + chunk)*256 + s*32 + dh] = t;
    }

    if (write_attn) {  // unnormalized p; scaled later by attn_scale
        float* ao = attn_out + (size_t)bh * 32768 + n0;
        for (int i = tid; i < 8192; i += 256)
            ao[(i >> 10) * 4096 + (i & 1023)] = attn_s[i];
    }
}

__global__ void attn_finalize(const float* __restrict__ upd_part,
                              const float* __restrict__ rs_part,
                              float* __restrict__ upd, float* __restrict__ invrs)
{
    int bh = blockIdx.x, tid = threadIdx.x;
    __shared__ float inv[8];
    if (tid < 8) {
        float t = 0.0f;
#pragma unroll
        for (int c = 0; c < 4; ++c) t += rs_part[(size_t)(bh*4 + c)*8 + tid];
        float v = 1.0f / fmaxf(t, 1e-12f);
        inv[tid] = v;
        invrs[bh*8 + tid] = v;
    }
    __syncthreads();
    int s = tid >> 5, dh = tid & 31;
    float t = 0.0f;
#pragma unroll
    for (int c = 0; c < 4; ++c) t += upd_part[(size_t)(bh*4 + c)*256 + s*32 + dh];
    int b = bh >> 3, h = bh & 7;
    upd[(size_t)(b*8 + s)*256 + h*32 + dh] = t * inv[s];
}

__global__ void attn_scale(float* __restrict__ ao, const float* __restrict__ invrs)
{
    int bh = blockIdx.x, tid = threadIdx.x;
    __shared__ float inv[8];
    if (tid < 8) inv[tid] = invrs[bh*8 + tid];
    __syncthreads();
    float* p = ao + (size_t)bh * 32768;
    for (int i = tid; i < 32768; i += 256)
        p[i] *= inv[i >> 12];
}

__global__ void gru_combine_kernel(const float* __restrict__ xg,
                                   const float* __restrict__ hg,
                                   float* __restrict__ slots)
{
    int idx = blockIdx.x * 256 + threadIdx.x;
    int row = idx >> 8, c = idx & 255;
    const float* x = xg + (size_t)row * 768;
    const float* h = hg + (size_t)row * 768;
    float r = 1.0f / (1.0f + expf(-(x[c]     + h[c])));
    float z = 1.0f / (1.0f + expf(-(x[256+c] + h[256+c])));
    float n = tanhf(x[512+c] + r * h[512+c]);
    slots[idx] = (1.0f - z) * n + z * slots[idx];
}

// ---------------- launcher ----------------------------------------------------
extern "C" void kernel_launch(void* const* d_in, const int* in_sizes, int n_in,
                              void* d_out, int out_size)
{
    const float* inp   = (const float*)d_in[0];
    const float* noise = (const float*)d_in[1];
    const float* smean = (const float*)d_in[2];
    const float* slogv = (const float*)d_in[3];
    const float* wq = (const float*)d_in[4];  const float* bq = (const float*)d_in[5];
    const float* wk = (const float*)d_in[6];  const float* bk = (const float*)d_in[7];
    const float* wv = (const float*)d_in[8];  const float* bv = (const float*)d_in[9];
    const float* wo = (const float*)d_in[10]; const float* bo = (const float*)d_in[11];
    const float* w_ih = (const float*)d_in[12]; const float* b_ih = (const float*)d_in[13];
    const float* w_hh = (const float*)d_in[14]; const float* b_hh = (const float*)d_in[15];
    const float* w1 = (const float*)d_in[16]; const float* b1 = (const float*)d_in[17];
    const float* w2 = (const float*)d_in[18]; const float* b2 = (const float*)d_in[19];
    const float* lin_w = (const float*)d_in[20]; const float* lin_b = (const float*)d_in[21];
    const float* ls_w  = (const float*)d_in[22]; const float* ls_b  = (const float*)d_in[23];
    const float* lff_w = (const float*)d_in[24]; const float* lff_b = (const float*)d_in[25];

    float* out      = (float*)d_out;
    float* attn_out = out + 131072;

    __nv_bfloat16 *a2, *wb2, *kbh, *vbh;
    float *slots,*qb,*upd,*upd2,*h1,*xg,*hg,*updp,*rsp,*invr;
    cudaGetSymbolAddress((void**)&a2,   g_a2);
    cudaGetSymbolAddress((void**)&wb2,  g_wb2);
    cudaGetSymbolAddress((void**)&kbh,  g_kbufh);
    cudaGetSymbolAddress((void**)&vbh,  g_vbufh);
    cudaGetSymbolAddress((void**)&slots,g_slots);
    cudaGetSymbolAddress((void**)&qb,   g_q);
    cudaGetSymbolAddress((void**)&upd,  g_upd);
    cudaGetSymbolAddress((void**)&upd2, g_upd2);
    cudaGetSymbolAddress((void**)&h1,   g_h1);
    cudaGetSymbolAddress((void**)&xg,   g_xg);
    cudaGetSymbolAddress((void**)&hg,   g_hg);
    cudaGetSymbolAddress((void**)&updp, g_updpart);
    cudaGetSymbolAddress((void**)&rsp,  g_rspart);
    cudaGetSymbolAddress((void**)&invr, g_invrs);

    cudaFuncSetAttribute(attention_part,
                         cudaFuncAttributeMaxDynamicSharedMemorySize, (int)ATT_SMEM);
    cudaFuncSetAttribute(kv_gemm_mma,
                         cudaFuncAttributeMaxDynamicSharedMemorySize, KV_SMEM);

    init_slots_kernel<<<BSc, 256>>>(noise, smean, slogv, slots);
    prep_w_kernel<<<512, 256>>>(wk, wv, wb2);
    ln_kv_kernel<<<Mc/8, 256>>>(inp, a2, lin_w, lin_b);
    kv_gemm_mma<<<dim3(4, Mc/128), 256, KV_SMEM>>>(a2, wb2, bk, bv, kbh, vbh);

    for (int it = 0; it < ITERS; ++it) {
        int last = (it == ITERS - 1);
        gemm512_kernel<<<dim3(16, 4), 256>>>(slots, wq, bq, qb, 256, 3, nullptr,
                                             ls_w, ls_b, nullptr, nullptr, nullptr, nullptr, 9999);
        attention_part<<<dim3(512, 4), 256, ATT_SMEM>>>(qb, kbh, vbh, updp, rsp, attn_out, last);
        attn_finalize<<<512, 256>>>(updp, rsp, upd, invr);
        if (last) attn_scale<<<512, 256>>>(attn_out, invr);
        gemm512_kernel<<<dim3(16, 4), 256>>>(upd, wo, bo, upd2, 256, 0, nullptr,
                                             nullptr, nullptr, nullptr, nullptr, nullptr, nullptr, 9999);
        gemm512_kernel<<<dim3(16, 24), 256>>>(upd2, w_ih, b_ih, xg, 768, 0, nullptr,
                                              nullptr, nullptr, slots, w_hh, b_hh, hg, 12);
        gru_combine_kernel<<<BSc, 256>>>(xg, hg, slots);
        gemm512_kernel<<<dim3(16, 4), 256>>>(slots, w1, b1, h1, 256, 1, nullptr,
                                             lff_w, lff_b, nullptr, nullptr, nullptr, nullptr, 9999);
        gemm512_kernel<<<dim3(16, 4), 256>>>(h1, w2, b2, last ? out : slots, 256, 2, slots,
                                             nullptr, nullptr, nullptr, nullptr, nullptr, nullptr, 9999);
    }
}

// round 10
// speedup vs baseline: 4.3954x; 1.3088x over previous
#include <cuda_runtime.h>
#include <cuda_bf16.h>
#include <cstdint>

#define ITERS 3
#define EPSc 1e-8f
#define LN_EPSc 1e-5f
#define Mc 262144   // B*N
#define BSc 512     // B*S

// ---------------- scratch (device globals) ----------------------------------
__device__ __nv_bfloat16 g_a2 [67108864]; // [M,256] bf16 of LN(x)
__device__ __nv_bfloat16 g_wb2[131072];   // [512 n][256 k] bf16 K-major
__device__ __nv_bfloat16 g_kbufh[67108864];// K [B,H,N,DH] bf16
__device__ __nv_bfloat16 g_vbufh[67108864];// V [B,H,N,DH] bf16
__device__ float g_slots[131072];
__device__ float g_q    [131072];
__device__ float g_upd  [131072];
__device__ float g_upd2 [131072];
__device__ float g_h1   [131072];
__device__ float g_xg   [393216];
__device__ float g_hg   [393216];
__device__ float g_updpart[524288];        // [bh*4+chunk][8s][32dh]
__device__ float g_rspart [16384];         // [bh*4+chunk][8s]
__device__ float g_invrs  [4096];          // [bh][8s]

__device__ __forceinline__ uint32_t smem_u32(const void* p) {
    uint32_t a;
    asm("{ .reg .u64 t; cvta.to.shared.u64 t, %1; cvt.u32.u64 %0, t; }" : "=r"(a) : "l"(p));
    return a;
}
__device__ __forceinline__ void cp_async16(uint32_t ds, const void* gp) {
    asm volatile("cp.async.cg.shared.global [%0], [%1], 16;" :: "r"(ds), "l"(gp));
}
#define CP_COMMIT() asm volatile("cp.async.commit_group;")
#define CP_WAIT1()  asm volatile("cp.async.wait_group 1;")
#define CP_WAIT0()  asm volatile("cp.async.wait_group 0;")
#define LDMX4(r0,r1,r2,r3,a) \
    asm volatile("ldmatrix.sync.aligned.m8n8.x4.shared.b16 {%0,%1,%2,%3}, [%4];" \
        : "=r"(r0),"=r"(r1),"=r"(r2),"=r"(r3) : "r"(a))
#define MMA16816(acc, a0,a1,a2,a3, b0,b1) \
    asm volatile("mma.sync.aligned.m16n8k16.row.col.f32.bf16.bf16.f32 " \
        "{%0,%1,%2,%3}, {%4,%5,%6,%7}, {%8,%9}, {%0,%1,%2,%3};" \
        : "+f"((acc)[0]), "+f"((acc)[1]), "+f"((acc)[2]), "+f"((acc)[3]) \
        : "r"(a0), "r"(a1), "r"(a2), "r"(a3), "r"(b0), "r"(b1))

// ---------------- misc small kernels -----------------------------------------
__global__ void init_slots_kernel(const float* __restrict__ noise,
                                  const float* __restrict__ mean,
                                  const float* __restrict__ logv,
                                  float* __restrict__ slots)
{
    int idx = blockIdx.x * 256 + threadIdx.x;
    int d = idx & 255;
    slots[idx] = mean[d] + expf(logv[d]) * noise[idx];
}

// LN(inputs) -> bf16 [M,256]
__global__ void ln_kv_kernel(const float* __restrict__ src, __nv_bfloat16* __restrict__ dst,
                             const float* __restrict__ w, const float* __restrict__ b)
{
    int row = blockIdx.x * 8 + (threadIdx.x >> 5);
    int lane = threadIdx.x & 31;
    const float4* r4 = (const float4*)(src + (size_t)row * 256);
    float4 v0 = r4[lane], v1 = r4[lane + 32];
    float s  = v0.x + v0.y + v0.z + v0.w + v1.x + v1.y + v1.z + v1.w;
    float sq = v0.x*v0.x + v0.y*v0.y + v0.z*v0.z + v0.w*v0.w
             + v1.x*v1.x + v1.y*v1.y + v1.z*v1.z + v1.w*v1.w;
#pragma unroll
    for (int o = 16; o > 0; o >>= 1) {
        s  += __shfl_xor_sync(~0u, s,  o);
        sq += __shfl_xor_sync(~0u, sq, o);
    }
    float mean = s * (1.0f/256.0f);
    float rstd = rsqrtf(sq * (1.0f/256.0f) - mean*mean + LN_EPSc);
    float4 wa = ((const float4*)w)[lane], wb = ((const float4*)w)[lane+32];
    float4 ba = ((const float4*)b)[lane], bb = ((const float4*)b)[lane+32];
    float4 o0, o1;
    o0.x=(v0.x-mean)*rstd*wa.x+ba.x; o0.y=(v0.y-mean)*rstd*wa.y+ba.y;
    o0.z=(v0.z-mean)*rstd*wa.z+ba.z; o0.w=(v0.w-mean)*rstd*wa.w+ba.w;
    o1.x=(v1.x-mean)*rstd*wb.x+bb.x; o1.y=(v1.y-mean)*rstd*wb.y+bb.y;
    o1.z=(v1.z-mean)*rstd*wb.z+bb.z; o1.w=(v1.w-mean)*rstd*wb.w+bb.w;
    __nv_bfloat16* dr = dst + (size_t)row * 256;
    __nv_bfloat162 h0; h0.x = __float2bfloat16(o0.x); h0.y = __float2bfloat16(o0.y);
    __nv_bfloat162 h1; h1.x = __float2bfloat16(o0.z); h1.y = __float2bfloat16(o0.w);
    __nv_bfloat162 h2; h2.x = __float2bfloat16(o1.x); h2.y = __float2bfloat16(o1.y);
    __nv_bfloat162 h3; h3.x = __float2bfloat16(o1.z); h3.y = __float2bfloat16(o1.w);
    ((__nv_bfloat162*)(dr + lane*4))[0] = h0;
    ((__nv_bfloat162*)(dr + lane*4))[1] = h1;
    ((__nv_bfloat162*)(dr + 128 + lane*4))[0] = h2;
    ((__nv_bfloat162*)(dr + 128 + lane*4))[1] = h3;
}

// W -> [n][k] K-major bf16 (n<256: wk, else wv)
__global__ void prep_w_kernel(const float* __restrict__ wk, const float* __restrict__ wv,
                              __nv_bfloat16* __restrict__ B2)
{
    int n = blockIdx.x;          // 0..511
    int k = threadIdx.x;         // 0..255
    const float* W = (n < 256) ? wk : wv;
    B2[(size_t)n * 256 + k] = __float2bfloat16(W[(size_t)k * 256 + (n & 255)]);
}

// ---------------- K/V GEMM: pure bf16, 4 chunks of K=64 ----------------------
// stage = [A 16K | B 16K] = 32 KB; 2 stages = 64 KB.
#define KV_SMEM (32768 * 2)
__global__ __launch_bounds__(256, 2)
void kv_gemm_mma(const __nv_bfloat16* __restrict__ A2, const __nv_bfloat16* __restrict__ B2,
                 const float* __restrict__ bk, const float* __restrict__ bv,
                 __nv_bfloat16* __restrict__ Kout, __nv_bfloat16* __restrict__ Vout)
{
    extern __shared__ char dsm[];
    uint32_t sbase = smem_u32(dsm);
    int tid = threadIdx.x, lane = tid & 31, wid = tid >> 5;
    int warp_m = wid & 1, warp_n = wid >> 1;       // 2 x 4 warps
    int cb  = blockIdx.x;                          // 0..3
    int m0  = blockIdx.y * 128;
    int mat = cb >> 1, nh = cb & 1;
    const float* bias = mat ? bv : bk;
    __nv_bfloat16* Out = mat ? Vout : Kout;

    float acc[4][4][4];
#pragma unroll
    for (int a = 0; a < 4; ++a)
#pragma unroll
        for (int b = 0; b < 4; ++b)
#pragma unroll
            for (int r = 0; r < 4; ++r) acc[a][b][r] = 0.0f;

    int lr = tid >> 3, lj = tid & 7;
    int brow_g = mat * 256 + nh * 128;

    int l7 = lane & 7, l15 = lane & 15, lhA = lane >> 4;
    int nrow_loc = (lane >> 4) * 8 + l7, hB = (lane >> 3) & 1;
    uint32_t aRow[4], bRow[2];
#pragma unroll
    for (int mt = 0; mt < 4; ++mt) aRow[mt] = (uint32_t)(warp_m*64 + mt*16 + l15) << 7;
#pragma unroll
    for (int g = 0; g < 2; ++g) bRow[g] = (uint32_t)(warp_n*32 + g*16 + nrow_loc) << 7;

#define LOAD_CHUNK(c, stg) do {                                               \
    uint32_t sa = sbase + (stg)*32768;                                        \
    int ko = (c)*64;                                                          \
    _Pragma("unroll")                                                         \
    for (int i = 0; i < 4; ++i) {                                             \
        int r = lr + i*32;                                                    \
        uint32_t so = (r<<7) + ((lj ^ (r&7))<<4);                             \
        cp_async16(sa + so, A2 + (size_t)(m0 + r)*256 + ko + lj*8);           \
        cp_async16(sa + 16384 + so, B2 + (size_t)(brow_g + r)*256 + ko + lj*8);\
    }                                                                         \
    CP_COMMIT();                                                              \
} while (0)

    LOAD_CHUNK(0, 0);
    LOAD_CHUNK(1, 1);

    for (int c = 0; c < 4; ++c) {
        if (c == 3) { CP_WAIT0(); } else { CP_WAIT1(); }
        __syncthreads();
        uint32_t sa = sbase + (c & 1) * 32768;
#pragma unroll
        for (int ks = 0; ks < 4; ++ks) {
            uint32_t achk = (uint32_t)(((2*ks + lhA) ^ l7) << 4);
            uint32_t bchk = (uint32_t)(((2*ks + hB)  ^ l7) << 4);
            uint32_t af[4][4], bf[2][4];
#pragma unroll
            for (int mt = 0; mt < 4; ++mt)
                LDMX4(af[mt][0], af[mt][1], af[mt][2], af[mt][3], sa + aRow[mt] + achk);
#pragma unroll
            for (int g = 0; g < 2; ++g)
                LDMX4(bf[g][0], bf[g][1], bf[g][2], bf[g][3], sa + 16384 + bRow[g] + bchk);
#pragma unroll
            for (int mt = 0; mt < 4; ++mt)
#pragma unroll
                for (int nt = 0; nt < 4; ++nt)
                    MMA16816(acc[mt][nt], af[mt][0], af[mt][1], af[mt][2], af[mt][3],
                             bf[nt>>1][(nt&1)*2], bf[nt>>1][(nt&1)*2+1]);
        }
        __syncthreads();
        if (c + 2 < 4) LOAD_CHUNK(c + 2, c & 1);
    }

    // epilogue: scatter bf16 to [B,H,N,DH]; head h = nh*4 + warp_n
    int col_base = nh * 128 + warp_n * 32;
    int h = col_base >> 5;
#pragma unroll
    for (int mt = 0; mt < 4; ++mt) {
#pragma unroll
        for (int half = 0; half < 2; ++half) {
            int m = m0 + warp_m * 64 + mt * 16 + (lane >> 2) + half * 8;
            int bi = m >> 12, nn = m & 4095;
            __nv_bfloat16* dst = Out + ((size_t)(bi * 8 + h) * 4096 + nn) * 32;
#pragma unroll
            for (int nt = 0; nt < 4; ++nt) {
                int dh = nt * 8 + (lane & 3) * 2;
                __nv_bfloat162 o;
                o.x = __float2bfloat16(acc[mt][nt][half*2+0] + bias[col_base + dh]);
                o.y = __float2bfloat16(acc[mt][nt][half*2+1] + bias[col_base + dh + 1]);
                *(__nv_bfloat162*)(dst + dh) = o;
            }
        }
    }
#undef LOAD_CHUNK
}

// ---------------- small GEMM (512 rows), optional fused input-LN -------------
__global__ __launch_bounds__(256)
void gemm512_kernel(const float* __restrict__ Ain, const float* __restrict__ Win,
                    const float* __restrict__ biasin, float* __restrict__ outin,
                    int Ncols, int mode, const float* __restrict__ resid,
                    const float* __restrict__ lnw, const float* __restrict__ lnb,
                    const float* __restrict__ A2, const float* __restrict__ W2,
                    const float* __restrict__ bias2, float* __restrict__ out2,
                    int y2)
{
    __shared__ float As[64][36];
    __shared__ float Bs[64][68];
    __shared__ float s_mean[32], s_rstd[32];
    int tid = threadIdx.x, tx = tid & 31, ty = tid >> 5;
    int c0 = tx*2, r0 = ty*4;
    int m0 = blockIdx.x * 32;
    int yb = blockIdx.y;
    const float* A = Ain; const float* W = Win; const float* bias = biasin;
    float* out = outin;
    if (yb >= y2) { A = A2; W = W2; bias = bias2; out = out2; yb -= y2; }
    int n0 = yb * 64;
    int do_ln = (lnw != nullptr);

    if (do_ln) {
        int r = ty * 4 + (tx >> 3);
        const float4* rp = (const float4*)(A + (size_t)(m0 + r) * 256);
        float s = 0.0f, sq = 0.0f;
        for (int j = (tx & 7); j < 64; j += 8) {
            float4 v = rp[j];
            s  += v.x + v.y + v.z + v.w;
            sq += v.x*v.x + v.y*v.y + v.z*v.z + v.w*v.w;
        }
#pragma unroll
        for (int o = 4; o > 0; o >>= 1) {
            s  += __shfl_xor_sync(~0u, s,  o);
            sq += __shfl_xor_sync(~0u, sq, o);
        }
        if ((tx & 7) == 0) {
            float mean = s * (1.0f/256.0f);
            s_mean[r] = mean;
            s_rstd[r] = rsqrtf(sq * (1.0f/256.0f) - mean*mean + LN_EPSc);
        }
    }
    __syncthreads();

    float acc[4][2] = {};
    for (int kt = 0; kt < 4; ++kt) {
        __syncthreads();
#pragma unroll
        for (int i = 0; i < 2; ++i) {
            int fid = tid*2 + i, ar = fid >> 4, kq = fid & 15;
            float4 va = *(const float4*)(A + (size_t)(m0+ar)*256 + kt*64 + kq*4);
            if (do_ln) {
                float mn = s_mean[ar], rs = s_rstd[ar];
                float4 lw = *(const float4*)(lnw + kt*64 + kq*4);
                float4 lb = *(const float4*)(lnb + kt*64 + kq*4);
                va.x = (va.x - mn)*rs*lw.x + lb.x;
                va.y = (va.y - mn)*rs*lw.y + lb.y;
                va.z = (va.z - mn)*rs*lw.z + lb.z;
                va.w = (va.w - mn)*rs*lw.w + lb.w;
            }
            As[kq*4+0][ar]=va.x; As[kq*4+1][ar]=va.y; As[kq*4+2][ar]=va.z; As[kq*4+3][ar]=va.w;
        }
#pragma unroll
        for (int j = 0; j < 4; ++j) {
            int fid = tid + j*256, br = fid >> 4, c4 = fid & 15;
            *(float4*)&Bs[br][c4*4] = *(const float4*)(W + (size_t)(kt*64+br)*Ncols + n0 + c4*4);
        }
        __syncthreads();
#pragma unroll 8
        for (int k = 0; k < 64; ++k) {
            float4 a4 = *(const float4*)&As[k][r0];
            float2 b2 = *(const float2*)&Bs[k][c0];
            acc[0][0]+=a4.x*b2.x; acc[0][1]+=a4.x*b2.y;
            acc[1][0]+=a4.y*b2.x; acc[1][1]+=a4.y*b2.y;
            acc[2][0]+=a4.z*b2.x; acc[2][1]+=a4.z*b2.y;
            acc[3][0]+=a4.w*b2.x; acc[3][1]+=a4.w*b2.y;
        }
    }
#pragma unroll
    for (int i = 0; i < 4; ++i)
#pragma unroll
        for (int j = 0; j < 2; ++j) {
            int m = m0 + r0 + i, n = n0 + c0 + j;
            float v = acc[i][j] + bias[n];
            if (mode == 0)      out[(size_t)m*Ncols + n] = v;
            else if (mode == 1) out[(size_t)m*Ncols + n] = fmaxf(v, 0.0f);
            else if (mode == 2) out[(size_t)m*256 + n] = resid[(size_t)m*256 + n] + v;
            else {
                int bq = m >> 3, s = m & 7, h = n >> 5, dh = n & 31;
                out[((size_t)(bq*8 + h)*8 + s)*32 + dh] = v;
            }
        }
}

// ---------------- attention, n-chunked (4 chunks of 1024), K+V bf16 ----------
#define ATT_SMEM ((8192 + 256 + 64 + 2048) * sizeof(float))
__global__ __launch_bounds__(256)
void attention_part(const float* __restrict__ q, const __nv_bfloat16* __restrict__ Kh,
                    const __nv_bfloat16* __restrict__ Vh,
                    float* __restrict__ upd_part, float* __restrict__ rs_part,
                    float* __restrict__ attn_out, int write_attn)
{
    extern __shared__ float sm[];
    float* attn_s = sm;                   // [8][1024]
    float* q_s    = sm + 8192;            // [8][32]
    float* red    = sm + 8192 + 256;      // [8][8]
    float* red2   = sm + 8192 + 256 + 64; // [8 warps][8 s][32 dh]
    int bh = blockIdx.x, chunk = blockIdx.y;
    int tid = threadIdx.x, lane = tid & 31, wid = tid >> 5;
    int n0 = chunk * 1024;

    q_s[tid] = q[(size_t)bh*256 + tid] * 0.0625f;  // scale = D^-0.5 = 1/16
    __syncthreads();

    float rs[8] = {};
    const __nv_bfloat16* Kb = Kh + (size_t)bh * 4096 * 32;
    for (int it = 0; it < 4; ++it) {
        int nl = it*256 + tid;
        const __nv_bfloat16* kr = Kb + (size_t)(n0 + nl) * 32;
        float d[8] = {};
#pragma unroll
        for (int c4 = 0; c4 < 4; ++c4) {
            float4 raw = *(const float4*)(kr + c4*8);
            const __nv_bfloat162* kp = (const __nv_bfloat162*)&raw;
            float2 k0 = __bfloat1622float2(kp[0]);
            float2 k1 = __bfloat1622float2(kp[1]);
            float2 k2 = __bfloat1622float2(kp[2]);
            float2 k3 = __bfloat1622float2(kp[3]);
#pragma unroll
            for (int s = 0; s < 8; ++s) {
                float4 qa = *(const float4*)(q_s + s*32 + c4*8);
                float4 qb = *(const float4*)(q_s + s*32 + c4*8 + 4);
                d[s] += k0.x*qa.x + k0.y*qa.y + k1.x*qa.z + k1.y*qa.w
                      + k2.x*qb.x + k2.y*qb.y + k3.x*qb.z + k3.y*qb.w;
            }
        }
        float mx = d[0];
#pragma unroll
        for (int s = 1; s < 8; ++s) mx = fmaxf(mx, d[s]);
        float e[8], sum = 0.0f;
#pragma unroll
        for (int s = 0; s < 8; ++s) { e[s] = __expf(d[s]-mx); sum += e[s]; }
        float inv = __fdividef(1.0f, sum);
#pragma unroll
        for (int s = 0; s < 8; ++s) {
            float p = e[s]*inv + EPSc;
            attn_s[s*1024 + nl] = p;
            rs[s] += p;
        }
    }
#pragma unroll
    for (int s = 0; s < 8; ++s)
#pragma unroll
        for (int o = 16; o > 0; o >>= 1) rs[s] += __shfl_xor_sync(~0u, rs[s], o);
    if (lane == 0)
#pragma unroll
        for (int s = 0; s < 8; ++s) red[wid*8 + s] = rs[s];
    __syncthreads();
    if (tid < 8) {
        float t = 0.0f;
#pragma unroll
        for (int w = 0; w < 8; ++w) t += red[w*8 + tid];
        rs_part[(size_t)(bh*4 + chunk)*8 + tid] = t;
    }

    // pass2: warp w owns n-substripe [w*128, (w+1)*128) of this chunk
    {
        const __nv_bfloat16* Vb = Vh + (size_t)bh * 4096 * 32;
        float acc[8] = {};
        int nb = wid * 128;
        for (int nl = nb; nl < nb + 128; nl += 4) {
            float4 a[8];
#pragma unroll
            for (int s = 0; s < 8; ++s) a[s] = *(const float4*)(attn_s + s*1024 + nl);
            int n = n0 + nl;
            float v0 = __bfloat162float(Vb[(size_t)(n+0)*32 + lane]);
            float v1 = __bfloat162float(Vb[(size_t)(n+1)*32 + lane]);
            float v2 = __bfloat162float(Vb[(size_t)(n+2)*32 + lane]);
            float v3 = __bfloat162float(Vb[(size_t)(n+3)*32 + lane]);
#pragma unroll
            for (int s = 0; s < 8; ++s)
                acc[s] += a[s].x*v0 + a[s].y*v1 + a[s].z*v2 + a[s].w*v3;
        }
#pragma unroll
        for (int s = 0; s < 8; ++s) red2[(wid*8 + s)*32 + lane] = acc[s];
    }
    __syncthreads();
    {
        int s = tid >> 5, dh = tid & 31;
        float t = 0.0f;
#pragma unroll
        for (int w = 0; w < 8; ++w) t += red2[(w*8 + s)*32 + dh];
        upd_part[(size_t)(bh*4 + chunk)*256 + s*32 + dh] = t;
    }

    if (write_attn) {  // unnormalized p; scaled later by attn_scale
        float* ao = attn_out + (size_t)bh * 32768 + n0;
        for (int i = tid; i < 8192; i += 256)
            ao[(i >> 10) * 4096 + (i & 1023)] = attn_s[i];
    }
}

__global__ void attn_finalize(const float* __restrict__ upd_part,
                              const float* __restrict__ rs_part,
                              float* __restrict__ upd, float* __restrict__ invrs)
{
    int bh = blockIdx.x, tid = threadIdx.x;
    __shared__ float inv[8];
    if (tid < 8) {
        float t = 0.0f;
#pragma unroll
        for (int c = 0; c < 4; ++c) t += rs_part[(size_t)(bh*4 + c)*8 + tid];
        float v = 1.0f / fmaxf(t, 1e-12f);
        inv[tid] = v;
        invrs[bh*8 + tid] = v;
    }
    __syncthreads();
    int s = tid >> 5, dh = tid & 31;
    float t = 0.0f;
#pragma unroll
    for (int c = 0; c < 4; ++c) t += upd_part[(size_t)(bh*4 + c)*256 + s*32 + dh];
    int b = bh >> 3, h = bh & 7;
    upd[(size_t)(b*8 + s)*256 + h*32 + dh] = t * inv[s];
}

__global__ void attn_scale(float* __restrict__ ao, const float* __restrict__ invrs)
{
    int bh = blockIdx.x, tid = threadIdx.x;
    __shared__ float inv[8];
    if (tid < 8) inv[tid] = invrs[bh*8 + tid];
    __syncthreads();
    float* p = ao + (size_t)bh * 32768;
    for (int i = tid; i < 32768; i += 256)
        p[i] *= inv[i >> 12];
}

__global__ void gru_combine_kernel(const float* __restrict__ xg,
                                   const float* __restrict__ hg,
                                   float* __restrict__ slots)
{
    int idx = blockIdx.x * 256 + threadIdx.x;
    int row = idx >> 8, c = idx & 255;
    const float* x = xg + (size_t)row * 768;
    const float* h = hg + (size_t)row * 768;
    float r = 1.0f / (1.0f + expf(-(x[c]     + h[c])));
    float z = 1.0f / (1.0f + expf(-(x[256+c] + h[256+c])));
    float n = tanhf(x[512+c] + r * h[512+c]);
    slots[idx] = (1.0f - z) * n + z * slots[idx];
}

// ---------------- launcher ----------------------------------------------------
extern "C" void kernel_launch(void* const* d_in, const int* in_sizes, int n_in,
                              void* d_out, int out_size)
{
    const float* inp   = (const float*)d_in[0];
    const float* noise = (const float*)d_in[1];
    const float* smean = (const float*)d_in[2];
    const float* slogv = (const float*)d_in[3];
    const float* wq = (const float*)d_in[4];  const float* bq = (const float*)d_in[5];
    const float* wk = (const float*)d_in[6];  const float* bk = (const float*)d_in[7];
    const float* wv = (const float*)d_in[8];  const float* bv = (const float*)d_in[9];
    const float* wo = (const float*)d_in[10]; const float* bo = (const float*)d_in[11];
    const float* w_ih = (const float*)d_in[12]; const float* b_ih = (const float*)d_in[13];
    const float* w_hh = (const float*)d_in[14]; const float* b_hh = (const float*)d_in[15];
    const float* w1 = (const float*)d_in[16]; const float* b1 = (const float*)d_in[17];
    const float* w2 = (const float*)d_in[18]; const float* b2 = (const float*)d_in[19];
    const float* lin_w = (const float*)d_in[20]; const float* lin_b = (const float*)d_in[21];
    const float* ls_w  = (const float*)d_in[22]; const float* ls_b  = (const float*)d_in[23];
    const float* lff_w = (const float*)d_in[24]; const float* lff_b = (const float*)d_in[25];

    float* out      = (float*)d_out;
    float* attn_out = out + 131072;

    __nv_bfloat16 *a2, *wb2, *kbh, *vbh;
    float *slots,*qb,*upd,*upd2,*h1,*xg,*hg,*updp,*rsp,*invr;
    cudaGetSymbolAddress((void**)&a2,   g_a2);
    cudaGetSymbolAddress((void**)&wb2,  g_wb2);
    cudaGetSymbolAddress((void**)&kbh,  g_kbufh);
    cudaGetSymbolAddress((void**)&vbh,  g_vbufh);
    cudaGetSymbolAddress((void**)&slots,g_slots);
    cudaGetSymbolAddress((void**)&qb,   g_q);
    cudaGetSymbolAddress((void**)&upd,  g_upd);
    cudaGetSymbolAddress((void**)&upd2, g_upd2);
    cudaGetSymbolAddress((void**)&h1,   g_h1);
    cudaGetSymbolAddress((void**)&xg,   g_xg);
    cudaGetSymbolAddress((void**)&hg,   g_hg);
    cudaGetSymbolAddress((void**)&updp, g_updpart);
    cudaGetSymbolAddress((void**)&rsp,  g_rspart);
    cudaGetSymbolAddress((void**)&invr, g_invrs);

    cudaFuncSetAttribute(attention_part,
                         cudaFuncAttributeMaxDynamicSharedMemorySize, (int)ATT_SMEM);
    cudaFuncSetAttribute(kv_gemm_mma,
                         cudaFuncAttributeMaxDynamicSharedMemorySize, KV_SMEM);

    init_slots_kernel<<<BSc, 256>>>(noise, smean, slogv, slots);
    prep_w_kernel<<<512, 256>>>(wk, wv, wb2);
    ln_kv_kernel<<<Mc/8, 256>>>(inp, a2, lin_w, lin_b);
    kv_gemm_mma<<<dim3(4, Mc/128), 256, KV_SMEM>>>(a2, wb2, bk, bv, kbh, vbh);

    for (int it = 0; it < ITERS; ++it) {
        int last = (it == ITERS - 1);
        gemm512_kernel<<<dim3(16, 4), 256>>>(slots, wq, bq, qb, 256, 3, nullptr,
                                             ls_w, ls_b, nullptr, nullptr, nullptr, nullptr, 9999);
        attention_part<<<dim3(512, 4), 256, ATT_SMEM>>>(qb, kbh, vbh, updp, rsp, attn_out, last);
        attn_finalize<<<512, 256>>>(updp, rsp, upd, invr);
        if (last) attn_scale<<<512, 256>>>(attn_out, invr);
        gemm512_kernel<<<dim3(16, 4), 256>>>(upd, wo, bo, upd2, 256, 0, nullptr,
                                             nullptr, nullptr, nullptr, nullptr, nullptr, nullptr, 9999);
        gemm512_kernel<<<dim3(16, 24), 256>>>(upd2, w_ih, b_ih, xg, 768, 0, nullptr,
                                              nullptr, nullptr, slots, w_hh, b_hh, hg, 12);
        gru_combine_kernel<<<BSc, 256>>>(xg, hg, slots);
        gemm512_kernel<<<dim3(16, 4), 256>>>(slots, w1, b1, h1, 256, 1, nullptr,
                                             lff_w, lff_b, nullptr, nullptr, nullptr, nullptr, 9999);
        gemm512_kernel<<<dim3(16, 4), 256>>>(h1, w2, b2, last ? out : slots, 256, 2, slots,
                                             nullptr, nullptr, nullptr, nullptr, nullptr, nullptr, 9999);
    }
}